// round 14
// baseline (speedup 1.0000x reference)
#include <cuda_runtime.h>
#include <cuda_bf16.h>
#include <math.h>

#define NN 2
#define CC 256
#define HH 96
#define WW 96
#define HS 48
#define PP 2304
#define COLS 4608
#define GG 8
#define DD 32
#define DPW 33

// ---------------- scratch ----------------
__device__ __align__(16) __nv_bfloat16 g_wA[3 * CC * CC];
__device__ __align__(16) __nv_bfloat16 g_wp[CC * CC];
__device__ __align__(16) __nv_bfloat16 g_xsT[COLS * CC];
__device__ __align__(16) float g_qkv[3 * CC * COLS];
__device__ __align__(16) float g_px[95 * CC];
__device__ __align__(16) float g_py[95 * CC];
__device__ __align__(16) float g_wxt[128 * CC];
__device__ __align__(16) float g_wyt[128 * CC];
__device__ __align__(16) float g_ex[16 * PP * 48];
__device__ __align__(16) float g_eyT[16 * 48 * PP];
__device__ __align__(16) float g_ek[16 * PP];
__device__ __align__(16) __nv_bfloat16 g_wt[16 * 48 * DPW * 48];
__device__ __align__(16) __nv_bfloat16 g_attT[COLS * CC];
__device__ __align__(16) float g_proj[CC * COLS];

// ---------------- helpers ----------------
__device__ __forceinline__ unsigned pack2(float2 f) {
    __nv_bfloat162 h = __float22bfloat162_rn(f);
    return *reinterpret_cast<unsigned*>(&h);
}
__device__ __forceinline__ unsigned hmul2u(unsigned a, __nv_bfloat162 b) {
    __nv_bfloat162 av = *reinterpret_cast<__nv_bfloat162*>(&a);
    __nv_bfloat162 r = __hmul2(av, b);
    return *reinterpret_cast<unsigned*>(&r);
}
__device__ __forceinline__ void mma16816(float d[4], const unsigned a[4], unsigned b0,
                                         unsigned b1) {
    asm volatile(
        "mma.sync.aligned.m16n8k16.row.col.f32.bf16.bf16.f32 "
        "{%0,%1,%2,%3}, {%4,%5,%6,%7}, {%8,%9}, {%0,%1,%2,%3};\n"
        : "+f"(d[0]), "+f"(d[1]), "+f"(d[2]), "+f"(d[3])
        : "r"(a[0]), "r"(a[1]), "r"(a[2]), "r"(a[3]), "r"(b0), "r"(b1));
}
__device__ __forceinline__ void cpa16(void* smem, const void* gmem) {
    unsigned saddr = (unsigned)__cvta_generic_to_shared(smem);
    asm volatile("cp.async.ca.shared.global [%0], [%1], 16;\n" ::"r"(saddr), "l"(gmem));
}
#define CPA_COMMIT asm volatile("cp.async.commit_group;\n" ::)
#define CPA_WAIT1 asm volatile("cp.async.wait_group 1;\n" ::)
#define CPA_WAIT0 asm volatile("cp.async.wait_group 0;\n" ::)

// ---------------- prep ----------------
__global__ void k_prep_w(const float* __restrict__ Wq, const float* __restrict__ Wk,
                         const float* __restrict__ Wv, const float* __restrict__ Wp,
                         const float* __restrict__ Wx, const float* __restrict__ Wy) {
    int b = blockIdx.x;
    int t = threadIdx.x;
    if (b < 256) {
        int i = b * 256 + t;
        g_wA[i] = __float2bfloat16(Wq[i]);
        g_wA[65536 + i] = __float2bfloat16(Wk[i]);
        g_wA[131072 + i] = __float2bfloat16(Wv[i]);
        g_wp[i] = __float2bfloat16(Wp[i]);
    } else {
        int f = b - 256;
        g_wxt[f * CC + t] = Wx[t * 128 + f];
        g_wyt[f * CC + t] = Wy[t * 128 + f];
    }
}

__global__ void __launch_bounds__(256) k_subT(const float* __restrict__ x) {
    __shared__ float tile[32][33];
    int col0 = blockIdx.x * 32, c0 = blockIdx.y * 32;
    int t = threadIdx.x, tx = t % 32, ty = t / 32;
#pragma unroll
    for (int j = 0; j < 4; j++) {
        int c = c0 + ty + j * 8;
        int col = col0 + tx;
        int n = col / PP, p = col % PP;
        int ph = p / HS, pw = p % HS;
        tile[ty + j * 8][tx] = x[((n * CC + c) * HH + ph * 2) * WW + pw * 2];
    }
    __syncthreads();
#pragma unroll
    for (int j = 0; j < 4; j++) {
        int col = col0 + ty + j * 8;
        int c = c0 + tx;
        g_xsT[(size_t)col * CC + c] = __float2bfloat16(tile[tx][ty + j * 8]);
    }
}

// ---------------- pos: grid (95, 8) ----------------
__global__ void __launch_bounds__(256) k_pos2() {
    __shared__ float bs[128];
    __shared__ float part[4][64];
    int dl = blockIdx.x;
    int y = blockIdx.y;
    int axis = y & 1;
    int quad = y >> 1;
    const float* w = axis ? g_wyt : g_wxt;
    float Dv = 2.0f * (float)(dl - 47);
    int t = threadIdx.x;
    if (t < 128) {
        int f = t & 63;
        float m = powf(1000.0f, (float)f * (1.0f / 64.0f));
        float a = Dv / m;
        bs[t] = (t < 64) ? sinf(a) : cosf(a);
    }
    __syncthreads();
    int chl = t & 63;
    int fg = t >> 6;
    int ch = quad * 64 + chl;
    float s = 0.f;
#pragma unroll
    for (int fo = 0; fo < 32; fo++) {
        int f = fg * 32 + fo;
        s += bs[f] * w[f * CC + ch];
    }
    part[fg][chl] = s;
    __syncthreads();
    if (t < 64) {
        float r = (part[0][t] + part[1][t]) + (part[2][t] + part[3][t]);
        float* dst = axis ? g_py : g_px;
        dst[dl * CC + quad * 64 + t] = r * 0.70710678118654752f;
    }
}

// ---------------- qkv GEMM: 256x128 tile, 512 thr ----------------
#define QKV_SMEM ((2 * 256 * 40 + 2 * 128 * 40) * 2)
__global__ void __launch_bounds__(512) k_gemm_qkv() {
    extern __shared__ __align__(16) __nv_bfloat16 qsm[];
    __nv_bfloat16* As = qsm;
    __nv_bfloat16* Bs = qsm + 2 * 256 * 40;
    int t = threadIdx.x, lane = t & 31, wid = t >> 5;
    int g = lane >> 2, tg = lane & 3;
    int wm = wid & 7, wn = wid >> 3;
    int m0 = blockIdx.y * 256, n0 = blockIdx.x * 128;
    float acc[2][8][4] = {};
#pragma unroll
    for (int jj = t; jj < 1536; jj += 512) {
        if (jj < 1024) {
            int row = jj >> 2, qv = jj & 3;
            cpa16(As + row * 40 + qv * 8, g_wA + (size_t)(m0 + row) * 256 + qv * 8);
        } else {
            int j2 = jj - 1024;
            int row = j2 >> 2, qv = j2 & 3;
            cpa16(Bs + row * 40 + qv * 8, g_xsT + (size_t)(n0 + row) * 256 + qv * 8);
        }
    }
    CPA_COMMIT;
    for (int it = 0; it < 8; it++) {
        int cur = it & 1, nxt = cur ^ 1;
        if (it < 7) {
            int kc = (it + 1) * 32;
#pragma unroll
            for (int jj = t; jj < 1536; jj += 512) {
                if (jj < 1024) {
                    int row = jj >> 2, qv = jj & 3;
                    cpa16(As + nxt * 10240 + row * 40 + qv * 8,
                          g_wA + (size_t)(m0 + row) * 256 + kc + qv * 8);
                } else {
                    int j2 = jj - 1024;
                    int row = j2 >> 2, qv = j2 & 3;
                    cpa16(Bs + nxt * 5120 + row * 40 + qv * 8,
                          g_xsT + (size_t)(n0 + row) * 256 + kc + qv * 8);
                }
            }
            CPA_COMMIT;
            CPA_WAIT1;
        } else {
            CPA_WAIT0;
        }
        __syncthreads();
#pragma unroll
        for (int k2 = 0; k2 < 2; k2++) {
            unsigned ah[2][4];
#pragma unroll
            for (int mt = 0; mt < 2; mt++) {
                int r = wm * 32 + mt * 16 + g;
                const unsigned* p0 = (const unsigned*)(As + cur * 10240 + r * 40);
                const unsigned* p1 = (const unsigned*)(As + cur * 10240 + (r + 8) * 40);
                ah[mt][0] = p0[k2 * 8 + tg];
                ah[mt][1] = p1[k2 * 8 + tg];
                ah[mt][2] = p0[k2 * 8 + 4 + tg];
                ah[mt][3] = p1[k2 * 8 + 4 + tg];
            }
#pragma unroll
            for (int nt = 0; nt < 8; nt++) {
                int nr = wn * 64 + nt * 8 + g;
                const unsigned* pbs = (const unsigned*)(Bs + cur * 5120 + nr * 40);
                unsigned b0 = pbs[k2 * 8 + tg], b1 = pbs[k2 * 8 + 4 + tg];
#pragma unroll
                for (int mt = 0; mt < 2; mt++) mma16816(acc[mt][nt], ah[mt], b0, b1);
            }
        }
        __syncthreads();
    }
#pragma unroll
    for (int mt = 0; mt < 2; mt++) {
        int r = m0 + wm * 32 + mt * 16 + g;
#pragma unroll
        for (int nt = 0; nt < 8; nt++) {
            int col = n0 + wn * 64 + nt * 8 + tg * 2;
            *(float2*)&g_qkv[(size_t)r * COLS + col] = make_float2(acc[mt][nt][0], acc[mt][nt][1]);
            *(float2*)&g_qkv[(size_t)(r + 8) * COLS + col] =
                make_float2(acc[mt][nt][2], acc[mt][nt][3]);
        }
    }
}

// ---------------- Wp GEMM: 128x128 tile, kc=32 ----------------
__global__ void __launch_bounds__(256) k_gemm_wp() {
    __shared__ __align__(16) __nv_bfloat16 As[2][128][40];
    __shared__ __align__(16) __nv_bfloat16 Bs[2][128][40];
    int t = threadIdx.x, lane = t & 31, wid = t >> 5;
    int g = lane >> 2, tg = lane & 3;
    int wm = wid & 3, wn = wid >> 2;
    int m0 = blockIdx.y * 128, n0 = blockIdx.x * 128;
    float acc[2][8][4] = {};
#pragma unroll
    for (int jj = t; jj < 512; jj += 256) {
        int row = jj >> 2, qv = jj & 3;
        cpa16(&As[0][row][qv * 8], g_wp + (size_t)(m0 + row) * 256 + qv * 8);
        cpa16(&Bs[0][row][qv * 8], g_attT + (size_t)(n0 + row) * 256 + qv * 8);
    }
    CPA_COMMIT;
    for (int it = 0; it < 8; it++) {
        int cur = it & 1, nxt = cur ^ 1;
        if (it < 7) {
            int kc = (it + 1) * 32;
#pragma unroll
            for (int jj = t; jj < 512; jj += 256) {
                int row = jj >> 2, qv = jj & 3;
                cpa16(&As[nxt][row][qv * 8], g_wp + (size_t)(m0 + row) * 256 + kc + qv * 8);
                cpa16(&Bs[nxt][row][qv * 8], g_attT + (size_t)(n0 + row) * 256 + kc + qv * 8);
            }
            CPA_COMMIT;
            CPA_WAIT1;
        } else {
            CPA_WAIT0;
        }
        __syncthreads();
#pragma unroll
        for (int k2 = 0; k2 < 2; k2++) {
            unsigned ah[2][4];
#pragma unroll
            for (int mt = 0; mt < 2; mt++) {
                int r = wm * 32 + mt * 16 + g;
                const unsigned* p0 = (const unsigned*)As[cur][r];
                const unsigned* p1 = (const unsigned*)As[cur][r + 8];
                ah[mt][0] = p0[k2 * 8 + tg];
                ah[mt][1] = p1[k2 * 8 + tg];
                ah[mt][2] = p0[k2 * 8 + 4 + tg];
                ah[mt][3] = p1[k2 * 8 + 4 + tg];
            }
#pragma unroll
            for (int nt = 0; nt < 8; nt++) {
                int nr = wn * 64 + nt * 8 + g;
                const unsigned* pbs = (const unsigned*)Bs[cur][nr];
                unsigned b0 = pbs[k2 * 8 + tg], b1 = pbs[k2 * 8 + 4 + tg];
#pragma unroll
                for (int mt = 0; mt < 2; mt++) mma16816(acc[mt][nt], ah[mt], b0, b1);
            }
        }
        __syncthreads();
    }
#pragma unroll
    for (int mt = 0; mt < 2; mt++) {
        int r = m0 + wm * 32 + mt * 16 + g;
#pragma unroll
        for (int nt = 0; nt < 8; nt++) {
            int col = n0 + wn * 64 + nt * 8 + tg * 2;
            *(float2*)&g_proj[(size_t)r * COLS + col] = make_float2(acc[mt][nt][0], acc[mt][nt][1]);
            *(float2*)&g_proj[(size_t)(r + 8) * COLS + col] =
                make_float2(acc[mt][nt][2], acc[mt][nt][3]);
        }
    }
}

// ---------------- ex/ey: float4 smem (stride 36) ----------------
__global__ void __launch_bounds__(256) k_exy() {
    int b = blockIdx.x;
    int h = b % HS;
    int ng = b / HS;
    int g = ng % GG, n = ng / GG;
    __shared__ __align__(16) float qs[48][36];
    __shared__ __align__(16) float pxs[95][36];
    __shared__ __align__(16) float pys[48][36];
    __shared__ float exm[48][49];
    __shared__ float eym[48][49];
    __shared__ float rmx[48], rmy[48];
    int t = threadIdx.x;
    for (int i = t; i < 48 * 32; i += 256) {
        int d = i / 48, w_ = i % 48;
        qs[w_][d] = g_qkv[(size_t)(g * DD + d) * COLS + n * PP + h * HS + w_];
    }
    for (int i = t; i < 95 * 8; i += 256) {
        int dl = i / 8, d4 = i % 8;
        *(float4*)&pxs[dl][d4 * 4] = *(const float4*)&g_px[dl * CC + g * DD + d4 * 4];
    }
    for (int i = t; i < 48 * 8; i += 256) {
        int u = i / 8, d4 = i % 8;
        *(float4*)&pys[u][d4 * 4] = *(const float4*)&g_py[(h - u + 47) * CC + g * DD + d4 * 4];
    }
    __syncthreads();
    for (int i = t; i < PP; i += 256) {
        int w_ = i / 48, v = i % 48;
        float s = 0.f, s2 = 0.f;
#pragma unroll
        for (int d4 = 0; d4 < 8; d4++) {
            float4 q4 = *(const float4*)&qs[w_][d4 * 4];
            float4 px4 = *(const float4*)&pxs[w_ - v + 47][d4 * 4];
            float4 py4 = *(const float4*)&pys[v][d4 * 4];
            s += q4.x * px4.x + q4.y * px4.y + q4.z * px4.z + q4.w * px4.w;
            s2 += q4.x * py4.x + q4.y * py4.y + q4.z * py4.z + q4.w * py4.w;
        }
        exm[w_][v] = s;
        eym[w_][v] = s2;
    }
    __syncthreads();
    if (t < 48) {
        float m = -1e30f;
        for (int v = 0; v < 48; v++) m = fmaxf(m, exm[t][v]);
        rmx[t] = m;
    } else if (t < 96) {
        int w_ = t - 48;
        float m = -1e30f;
        for (int u = 0; u < 48; u++) m = fmaxf(m, eym[w_][u]);
        rmy[w_] = m;
    }
    __syncthreads();
    for (int i = t; i < PP; i += 256) {
        int w_ = i / 48, v = i % 48;
        g_ex[((size_t)ng * PP + h * HS + w_) * 48 + v] = expf(exm[w_][v] - rmx[w_]);
    }
    for (int i = t; i < PP; i += 256) {
        int u = i / 48, w_ = i % 48;
        g_eyT[((size_t)ng * 48 + u) * PP + h * HS + w_] = expf(eym[w_][u] - rmy[w_]);
    }
}

// ---------------- ek fused: dot + max + exp ----------------
__global__ void __launch_bounds__(256) k_ekf(const float* __restrict__ ab) {
    __shared__ float red[256];
    int ng = blockIdx.x;
    int g = ng % GG, n = ng / GG;
    int t = threadIdx.x;
    float ekv[9];
    float m = -1e30f;
#pragma unroll
    for (int j = 0; j < 9; j++) {
        int uv = j * 256 + t;
        float s = 0.f;
#pragma unroll
        for (int d = 0; d < 32; d++)
            s += ab[g * DD + d] * g_qkv[(size_t)(CC + g * DD + d) * COLS + n * PP + uv];
        ekv[j] = s;
        m = fmaxf(m, s);
    }
    red[t] = m;
    __syncthreads();
    for (int s = 128; s > 0; s >>= 1) {
        if (t < s) red[t] = fmaxf(red[t], red[t + s]);
        __syncthreads();
    }
    float mk = red[0];
#pragma unroll
    for (int j = 0; j < 9; j++) g_ek[(size_t)ng * PP + j * 256 + t] = expf(ekv[j] - mk);
}

// ---------------- Wt bf16 [ng][u][33][48], flat 8/thread ----------------
__global__ void k_wt8() {
    int i = (blockIdx.x * 256 + threadIdx.x) * 8;
    int v = i % 48;
    int d = (i / 48) % DPW;
    int u = (i / (48 * DPW)) % 48;
    int ng = i / (48 * DPW * 48);
    int g = ng % GG, n = ng / GG;
    size_t eko = (size_t)ng * PP + u * 48 + v;
    float4 e0 = *(const float4*)&g_ek[eko];
    float4 e1 = *(const float4*)&g_ek[eko + 4];
    unsigned r[4];
    if (d < 32) {
        size_t vo = (size_t)(2 * CC + g * DD + d) * COLS + n * PP + u * 48 + v;
        float4 v0 = *(const float4*)&g_qkv[vo];
        float4 v1 = *(const float4*)&g_qkv[vo + 4];
        r[0] = pack2(make_float2(e0.x * v0.x, e0.y * v0.y));
        r[1] = pack2(make_float2(e0.z * v0.z, e0.w * v0.w));
        r[2] = pack2(make_float2(e1.x * v1.x, e1.y * v1.y));
        r[3] = pack2(make_float2(e1.z * v1.z, e1.w * v1.w));
    } else {
        r[0] = pack2(make_float2(e0.x, e0.y));
        r[1] = pack2(make_float2(e0.z, e0.w));
        r[2] = pack2(make_float2(e1.x, e1.y));
        r[3] = pack2(make_float2(e1.z, e1.w));
    }
    *(uint4*)&g_wt[i] = *(uint4*)r;
}

// ---------------- attention + Z fused in MMA (R10 form: 256 thr, scalar LDS) ----
#define WT_BUF (8 * 40 * 56)
#define ATT_SMEM (24576 + 2 * WT_BUF * 2)
__global__ void __launch_bounds__(256) k_attn_mma() {
    extern __shared__ __align__(16) char sm[];
    __nv_bfloat16* Eys = (__nv_bfloat16*)sm;
    __nv_bfloat16* Wth = (__nv_bfloat16*)(sm + 24576);
    int ng = blockIdx.y;
    int q0 = blockIdx.x * 256;
    int t = threadIdx.x, lane = t & 31, wid = t >> 5;
    int g = lane >> 2, tg = lane & 3;
    const __nv_bfloat16* wt_g = g_wt + (size_t)ng * 48 * DPW * 48;
    {
        unsigned* wz = (unsigned*)Wth;
        for (int j = t; j < 3136; j += 256) {
            int cc = j % 28;
            int row = j / 28;
            int uu = row % 8;
            int dd = 33 + (row / 8) % 7;
            int bb = row / 56;
            wz[bb * (WT_BUF / 2) + (uu * 40 + dd) * 28 + cc] = 0u;
        }
    }
    for (int j = t; j < 1584; j += 256) {
        int vq = j % 6, dd = (j / 6) % 33, uu = j / 198;
        cpa16(&Wth[(uu * 40 + dd) * 56 + vq * 8],
              wt_g + ((size_t)uu * DPW + dd) * 48 + vq * 8);
    }
    CPA_COMMIT;
    for (int i = t; i < 48 * 128; i += 256) {
        int u = i >> 7, qp = i & 127;
        float2 v2 = *(const float2*)&g_eyT[((size_t)ng * 48 + u) * PP + q0 + qp * 2];
        *(unsigned*)&Eys[u * 256 + qp * 2] = pack2(v2);
    }
    int qw = q0 + wid * 32;
    const float* exb = g_ex + (size_t)ng * PP * 48;
    unsigned exh[2][3][4];
#pragma unroll
    for (int mt = 0; mt < 2; mt++) {
        int qr0 = qw + mt * 16 + g, qr1 = qr0 + 8;
#pragma unroll
        for (int ks = 0; ks < 3; ks++) {
            int v0 = ks * 16 + tg * 2;
            exh[mt][ks][0] = pack2(*(const float2*)&exb[(size_t)qr0 * 48 + v0]);
            exh[mt][ks][1] = pack2(*(const float2*)&exb[(size_t)qr1 * 48 + v0]);
            exh[mt][ks][2] = pack2(*(const float2*)&exb[(size_t)qr0 * 48 + v0 + 8]);
            exh[mt][ks][3] = pack2(*(const float2*)&exb[(size_t)qr1 * 48 + v0 + 8]);
        }
    }
    float acc[2][5][4] = {};
    for (int it = 0; it < 6; it++) {
        int cur = it & 1, nxt = cur ^ 1;
        if (it < 5) {
            int uc = (it + 1) * 8;
            for (int j = t; j < 1584; j += 256) {
                int vq = j % 6, dd = (j / 6) % 33, uu = j / 198;
                cpa16(&Wth[nxt * WT_BUF + (uu * 40 + dd) * 56 + vq * 8],
                      wt_g + ((size_t)(uc + uu) * DPW + dd) * 48 + vq * 8);
            }
            CPA_COMMIT;
            CPA_WAIT1;
        } else {
            CPA_WAIT0;
        }
        __syncthreads();
#pragma unroll
        for (int uu = 0; uu < 8; uu++) {
            int u = it * 8 + uu;
            unsigned sa[2][3][4];
#pragma unroll
            for (int mt = 0; mt < 2; mt++) {
                __nv_bfloat162 e0 =
                    __bfloat162bfloat162(Eys[u * 256 + wid * 32 + mt * 16 + g]);
                __nv_bfloat162 e1 =
                    __bfloat162bfloat162(Eys[u * 256 + wid * 32 + mt * 16 + g + 8]);
#pragma unroll
                for (int ks = 0; ks < 3; ks++) {
                    sa[mt][ks][0] = hmul2u(exh[mt][ks][0], e0);
                    sa[mt][ks][1] = hmul2u(exh[mt][ks][1], e1);
                    sa[mt][ks][2] = hmul2u(exh[mt][ks][2], e0);
                    sa[mt][ks][3] = hmul2u(exh[mt][ks][3], e1);
                }
            }
            const unsigned* pbh = (const unsigned*)(Wth + cur * WT_BUF + uu * 40 * 56);
#pragma unroll
            for (int nt = 0; nt < 5; nt++) {
#pragma unroll
                for (int ks = 0; ks < 3; ks++) {
                    int widx = (nt * 8 + g) * 28 + ks * 8 + tg;
                    unsigned b0 = pbh[widx], b1 = pbh[widx + 4];
                    mma16816(acc[0][nt], sa[0][ks], b0, b1);
                    mma16816(acc[1][nt], sa[1][ks], b0, b1);
                }
            }
        }
        __syncthreads();
    }
    int n = ng >> 3, gh = ng & 7;
    int src = (lane >> 2) << 2;
#pragma unroll
    for (int mt = 0; mt < 2; mt++) {
        int qr0 = qw + mt * 16 + g, qr1 = qr0 + 8;
        float z0 = __shfl_sync(0xffffffffu, acc[mt][4][0], src);
        float z1 = __shfl_sync(0xffffffffu, acc[mt][4][2], src);
        float zi0 = 1.0f / z0, zi1 = 1.0f / z1;
        size_t col0 = (size_t)(n * PP + qr0) * CC;
        size_t col1 = (size_t)(n * PP + qr1) * CC;
#pragma unroll
        for (int nt = 0; nt < 4; nt++) {
            int c = gh * DD + nt * 8 + tg * 2;
            __nv_bfloat162 b0 = __float22bfloat162_rn(
                make_float2(acc[mt][nt][0] * zi0, acc[mt][nt][1] * zi0));
            __nv_bfloat162 b1 = __float22bfloat162_rn(
                make_float2(acc[mt][nt][2] * zi1, acc[mt][nt][3] * zi1));
            *(__nv_bfloat162*)&g_attT[col0 + c] = b0;
            *(__nv_bfloat162*)&g_attT[col1 + c] = b1;
        }
    }
}

// ---------------- bilinear upsample + bias + residual, 4-wide ----------------
__device__ __forceinline__ void taps48(int o, int& i0, int& i1, float& w0, float& w1) {
    int tt = o >> 1;
    if ((o & 1) == 0) {
        if (tt == 0) { i0 = 0; i1 = 0; w0 = 1.f; w1 = 0.f; }
        else { i0 = tt - 1; i1 = tt; w0 = 0.25f; w1 = 0.75f; }
    } else {
        if (tt == 47) { i0 = 47; i1 = 47; w0 = 1.f; w1 = 0.f; }
        else { i0 = tt; i1 = tt + 1; w0 = 0.75f; w1 = 0.25f; }
    }
}

__global__ void k_final4(const float* __restrict__ x, const float* __restrict__ bp,
                         const float* __restrict__ gamma, float* __restrict__ out) {
    int e = (blockIdx.x * 256 + threadIdx.x) * 4;
    int j0 = e % WW;
    int r = (e / WW) % HH;
    int c = (e / (HH * WW)) % CC;
    int n = e / (CC * HH * WW);
    int r0, r1;
    float rw0, rw1;
    taps48(r, r0, r1, rw0, rw1);
    const float* pr0 = g_proj + (size_t)c * COLS + n * PP + r0 * HS;
    const float* pr1 = g_proj + (size_t)c * COLS + n * PP + r1 * HS;
    float4 xr = *(const float4*)&x[e];
    float gmv = gamma[0];
    float bpv = bp[c];
    float res[4];
    float xv[4] = {xr.x, xr.y, xr.z, xr.w};
#pragma unroll
    for (int jj = 0; jj < 4; jj++) {
        int c0, c1;
        float cw0, cw1;
        taps48(j0 + jj, c0, c1, cw0, cw1);
        float v00 = pr0[c0], v01 = pr0[c1];
        float v10 = pr1[c0], v11 = pr1[c1];
        float bi = rw0 * (cw0 * v00 + cw1 * v01) + rw1 * (cw0 * v10 + cw1 * v11);
        res[jj] = gmv * (bi + bpv) + xv[jj];
    }
    *(float4*)&out[e] = make_float4(res[0], res[1], res[2], res[3]);
}

// ---------------- launch ----------------
extern "C" void kernel_launch(void* const* d_in, const int* in_sizes, int n_in,
                              void* d_out, int out_size) {
    (void)in_sizes; (void)n_in; (void)out_size;
    const float* x = (const float*)d_in[0];
    const float* Wq = (const float*)d_in[1];
    const float* Wk = (const float*)d_in[2];
    const float* Wv = (const float*)d_in[3];
    const float* Wx = (const float*)d_in[4];
    const float* Wy = (const float*)d_in[5];
    const float* ab = (const float*)d_in[6];
    const float* Wp = (const float*)d_in[7];
    const float* bp = (const float*)d_in[8];
    const float* gamma = (const float*)d_in[9];
    float* out = (float*)d_out;

    cudaFuncSetAttribute(k_attn_mma, cudaFuncAttributeMaxDynamicSharedMemorySize,
                         ATT_SMEM);
    cudaFuncSetAttribute(k_gemm_qkv, cudaFuncAttributeMaxDynamicSharedMemorySize,
                         QKV_SMEM);

    k_prep_w<<<384, 256>>>(Wq, Wk, Wv, Wp, Wx, Wy);
    k_subT<<<dim3(COLS / 32, CC / 32), 256>>>(x);
    k_pos2<<<dim3(95, 8), 256>>>();
    k_gemm_qkv<<<dim3(36, 3), 512, QKV_SMEM>>>();
    k_exy<<<16 * HS, 256>>>();
    k_ekf<<<16, 256>>>(ab);
    k_wt8<<<(16 * 48 * DPW * 48) / 2048, 256>>>();
    k_attn_mma<<<dim3(PP / 256, 16), 256, ATT_SMEM>>>();
    k_gemm_wp<<<dim3(36, 2), 256>>>();
    k_final4<<<(NN * CC * HH * WW) / 1024, 256>>>(x, bp, gamma, out);
}

// round 15
// speedup vs baseline: 1.4763x; 1.4763x over previous
#include <cuda_runtime.h>
#include <cuda_bf16.h>
#include <math.h>

#define NN 2
#define CC 256
#define HH 96
#define WW 96
#define HS 48
#define PP 2304
#define COLS 4608
#define GG 8
#define DD 32
#define DPW 33

// ---------------- scratch ----------------
__device__ __align__(16) __nv_bfloat16 g_wA[3 * CC * CC];
__device__ __align__(16) __nv_bfloat16 g_wp[CC * CC];
__device__ __align__(16) __nv_bfloat16 g_xsT[COLS * CC];
__device__ __align__(16) float g_qkv[3 * CC * COLS];
__device__ __align__(16) float g_px[95 * CC];
__device__ __align__(16) float g_py[95 * CC];
__device__ __align__(16) float g_wxt[128 * CC];
__device__ __align__(16) float g_wyt[128 * CC];
__device__ __align__(16) float g_ex[16 * PP * 48];
__device__ __align__(16) float g_eyT[16 * 48 * PP];
__device__ __align__(16) float g_ek[16 * PP];
__device__ __align__(16) __nv_bfloat16 g_wt[16 * 48 * DPW * 48];
__device__ __align__(16) __nv_bfloat16 g_attT[COLS * CC];
__device__ __align__(16) float g_proj[CC * COLS];

// ---------------- helpers ----------------
__device__ __forceinline__ unsigned pack2(float2 f) {
    __nv_bfloat162 h = __float22bfloat162_rn(f);
    return *reinterpret_cast<unsigned*>(&h);
}
__device__ __forceinline__ unsigned hmul2u(unsigned a, __nv_bfloat162 b) {
    __nv_bfloat162 av = *reinterpret_cast<__nv_bfloat162*>(&a);
    __nv_bfloat162 r = __hmul2(av, b);
    return *reinterpret_cast<unsigned*>(&r);
}
__device__ __forceinline__ void mma16816(float d[4], const unsigned a[4], unsigned b0,
                                         unsigned b1) {
    asm volatile(
        "mma.sync.aligned.m16n8k16.row.col.f32.bf16.bf16.f32 "
        "{%0,%1,%2,%3}, {%4,%5,%6,%7}, {%8,%9}, {%0,%1,%2,%3};\n"
        : "+f"(d[0]), "+f"(d[1]), "+f"(d[2]), "+f"(d[3])
        : "r"(a[0]), "r"(a[1]), "r"(a[2]), "r"(a[3]), "r"(b0), "r"(b1));
}
__device__ __forceinline__ void cpa16(void* smem, const void* gmem) {
    unsigned saddr = (unsigned)__cvta_generic_to_shared(smem);
    asm volatile("cp.async.ca.shared.global [%0], [%1], 16;\n" ::"r"(saddr), "l"(gmem));
}
#define CPA_COMMIT asm volatile("cp.async.commit_group;\n" ::)
#define CPA_WAIT1 asm volatile("cp.async.wait_group 1;\n" ::)
#define CPA_WAIT0 asm volatile("cp.async.wait_group 0;\n" ::)

// ---------------- prep ----------------
__global__ void k_prep_w(const float* __restrict__ Wq, const float* __restrict__ Wk,
                         const float* __restrict__ Wv, const float* __restrict__ Wp,
                         const float* __restrict__ Wx, const float* __restrict__ Wy) {
    int b = blockIdx.x;
    int t = threadIdx.x;
    if (b < 256) {
        int i = b * 256 + t;
        g_wA[i] = __float2bfloat16(Wq[i]);
        g_wA[65536 + i] = __float2bfloat16(Wk[i]);
        g_wA[131072 + i] = __float2bfloat16(Wv[i]);
        g_wp[i] = __float2bfloat16(Wp[i]);
    } else {
        int f = b - 256;
        g_wxt[f * CC + t] = Wx[t * 128 + f];
        g_wyt[f * CC + t] = Wy[t * 128 + f];
    }
}

__global__ void __launch_bounds__(256) k_subT(const float* __restrict__ x) {
    __shared__ float tile[32][33];
    int col0 = blockIdx.x * 32, c0 = blockIdx.y * 32;
    int t = threadIdx.x, tx = t % 32, ty = t / 32;
#pragma unroll
    for (int j = 0; j < 4; j++) {
        int c = c0 + ty + j * 8;
        int col = col0 + tx;
        int n = col / PP, p = col % PP;
        int ph = p / HS, pw = p % HS;
        tile[ty + j * 8][tx] = x[((n * CC + c) * HH + ph * 2) * WW + pw * 2];
    }
    __syncthreads();
#pragma unroll
    for (int j = 0; j < 4; j++) {
        int col = col0 + ty + j * 8;
        int c = c0 + tx;
        g_xsT[(size_t)col * CC + c] = __float2bfloat16(tile[tx][ty + j * 8]);
    }
}

// ---------------- pos: grid (95, 8) ----------------
__global__ void __launch_bounds__(256) k_pos2() {
    __shared__ float bs[128];
    __shared__ float part[4][64];
    int dl = blockIdx.x;
    int y = blockIdx.y;
    int axis = y & 1;
    int quad = y >> 1;
    const float* w = axis ? g_wyt : g_wxt;
    float Dv = 2.0f * (float)(dl - 47);
    int t = threadIdx.x;
    if (t < 128) {
        int f = t & 63;
        float m = powf(1000.0f, (float)f * (1.0f / 64.0f));
        float a = Dv / m;
        bs[t] = (t < 64) ? sinf(a) : cosf(a);
    }
    __syncthreads();
    int chl = t & 63;
    int fg = t >> 6;
    int ch = quad * 64 + chl;
    float s = 0.f;
#pragma unroll
    for (int fo = 0; fo < 32; fo++) {
        int f = fg * 32 + fo;
        s += bs[f] * w[f * CC + ch];
    }
    part[fg][chl] = s;
    __syncthreads();
    if (t < 64) {
        float r = (part[0][t] + part[1][t]) + (part[2][t] + part[3][t]);
        float* dst = axis ? g_py : g_px;
        dst[dl * CC + quad * 64 + t] = r * 0.70710678118654752f;
    }
}

// ---------------- qkv GEMM: 256x128 tile, 512 thr ----------------
#define QKV_SMEM ((2 * 256 * 40 + 2 * 128 * 40) * 2)
__global__ void __launch_bounds__(512) k_gemm_qkv() {
    extern __shared__ __align__(16) __nv_bfloat16 qsm[];
    __nv_bfloat16* As = qsm;
    __nv_bfloat16* Bs = qsm + 2 * 256 * 40;
    int t = threadIdx.x, lane = t & 31, wid = t >> 5;
    int g = lane >> 2, tg = lane & 3;
    int wm = wid & 7, wn = wid >> 3;
    int m0 = blockIdx.y * 256, n0 = blockIdx.x * 128;
    float acc[2][8][4] = {};
#pragma unroll
    for (int jj = t; jj < 1536; jj += 512) {
        if (jj < 1024) {
            int row = jj >> 2, qv = jj & 3;
            cpa16(As + row * 40 + qv * 8, g_wA + (size_t)(m0 + row) * 256 + qv * 8);
        } else {
            int j2 = jj - 1024;
            int row = j2 >> 2, qv = j2 & 3;
            cpa16(Bs + row * 40 + qv * 8, g_xsT + (size_t)(n0 + row) * 256 + qv * 8);
        }
    }
    CPA_COMMIT;
    for (int it = 0; it < 8; it++) {
        int cur = it & 1, nxt = cur ^ 1;
        if (it < 7) {
            int kc = (it + 1) * 32;
#pragma unroll
            for (int jj = t; jj < 1536; jj += 512) {
                if (jj < 1024) {
                    int row = jj >> 2, qv = jj & 3;
                    cpa16(As + nxt * 10240 + row * 40 + qv * 8,
                          g_wA + (size_t)(m0 + row) * 256 + kc + qv * 8);
                } else {
                    int j2 = jj - 1024;
                    int row = j2 >> 2, qv = j2 & 3;
                    cpa16(Bs + nxt * 5120 + row * 40 + qv * 8,
                          g_xsT + (size_t)(n0 + row) * 256 + kc + qv * 8);
                }
            }
            CPA_COMMIT;
            CPA_WAIT1;
        } else {
            CPA_WAIT0;
        }
        __syncthreads();
#pragma unroll
        for (int k2 = 0; k2 < 2; k2++) {
            unsigned ah[2][4];
#pragma unroll
            for (int mt = 0; mt < 2; mt++) {
                int r = wm * 32 + mt * 16 + g;
                const unsigned* p0 = (const unsigned*)(As + cur * 10240 + r * 40);
                const unsigned* p1 = (const unsigned*)(As + cur * 10240 + (r + 8) * 40);
                ah[mt][0] = p0[k2 * 8 + tg];
                ah[mt][1] = p1[k2 * 8 + tg];
                ah[mt][2] = p0[k2 * 8 + 4 + tg];
                ah[mt][3] = p1[k2 * 8 + 4 + tg];
            }
#pragma unroll
            for (int nt = 0; nt < 8; nt++) {
                int nr = wn * 64 + nt * 8 + g;
                const unsigned* pbs = (const unsigned*)(Bs + cur * 5120 + nr * 40);
                unsigned b0 = pbs[k2 * 8 + tg], b1 = pbs[k2 * 8 + 4 + tg];
#pragma unroll
                for (int mt = 0; mt < 2; mt++) mma16816(acc[mt][nt], ah[mt], b0, b1);
            }
        }
        __syncthreads();
    }
#pragma unroll
    for (int mt = 0; mt < 2; mt++) {
        int r = m0 + wm * 32 + mt * 16 + g;
#pragma unroll
        for (int nt = 0; nt < 8; nt++) {
            int col = n0 + wn * 64 + nt * 8 + tg * 2;
            *(float2*)&g_qkv[(size_t)r * COLS + col] = make_float2(acc[mt][nt][0], acc[mt][nt][1]);
            *(float2*)&g_qkv[(size_t)(r + 8) * COLS + col] =
                make_float2(acc[mt][nt][2], acc[mt][nt][3]);
        }
    }
}

// ---------------- Wp GEMM: 128x128 tile, kc=32 ----------------
__global__ void __launch_bounds__(256) k_gemm_wp() {
    __shared__ __align__(16) __nv_bfloat16 As[2][128][40];
    __shared__ __align__(16) __nv_bfloat16 Bs[2][128][40];
    int t = threadIdx.x, lane = t & 31, wid = t >> 5;
    int g = lane >> 2, tg = lane & 3;
    int wm = wid & 3, wn = wid >> 2;
    int m0 = blockIdx.y * 128, n0 = blockIdx.x * 128;
    float acc[2][8][4] = {};
#pragma unroll
    for (int jj = t; jj < 512; jj += 256) {
        int row = jj >> 2, qv = jj & 3;
        cpa16(&As[0][row][qv * 8], g_wp + (size_t)(m0 + row) * 256 + qv * 8);
        cpa16(&Bs[0][row][qv * 8], g_attT + (size_t)(n0 + row) * 256 + qv * 8);
    }
    CPA_COMMIT;
    for (int it = 0; it < 8; it++) {
        int cur = it & 1, nxt = cur ^ 1;
        if (it < 7) {
            int kc = (it + 1) * 32;
#pragma unroll
            for (int jj = t; jj < 512; jj += 256) {
                int row = jj >> 2, qv = jj & 3;
                cpa16(&As[nxt][row][qv * 8], g_wp + (size_t)(m0 + row) * 256 + kc + qv * 8);
                cpa16(&Bs[nxt][row][qv * 8], g_attT + (size_t)(n0 + row) * 256 + kc + qv * 8);
            }
            CPA_COMMIT;
            CPA_WAIT1;
        } else {
            CPA_WAIT0;
        }
        __syncthreads();
#pragma unroll
        for (int k2 = 0; k2 < 2; k2++) {
            unsigned ah[2][4];
#pragma unroll
            for (int mt = 0; mt < 2; mt++) {
                int r = wm * 32 + mt * 16 + g;
                const unsigned* p0 = (const unsigned*)As[cur][r];
                const unsigned* p1 = (const unsigned*)As[cur][r + 8];
                ah[mt][0] = p0[k2 * 8 + tg];
                ah[mt][1] = p1[k2 * 8 + tg];
                ah[mt][2] = p0[k2 * 8 + 4 + tg];
                ah[mt][3] = p1[k2 * 8 + 4 + tg];
            }
#pragma unroll
            for (int nt = 0; nt < 8; nt++) {
                int nr = wn * 64 + nt * 8 + g;
                const unsigned* pbs = (const unsigned*)Bs[cur][nr];
                unsigned b0 = pbs[k2 * 8 + tg], b1 = pbs[k2 * 8 + 4 + tg];
#pragma unroll
                for (int mt = 0; mt < 2; mt++) mma16816(acc[mt][nt], ah[mt], b0, b1);
            }
        }
        __syncthreads();
    }
#pragma unroll
    for (int mt = 0; mt < 2; mt++) {
        int r = m0 + wm * 32 + mt * 16 + g;
#pragma unroll
        for (int nt = 0; nt < 8; nt++) {
            int col = n0 + wn * 64 + nt * 8 + tg * 2;
            *(float2*)&g_proj[(size_t)r * COLS + col] = make_float2(acc[mt][nt][0], acc[mt][nt][1]);
            *(float2*)&g_proj[(size_t)(r + 8) * COLS + col] =
                make_float2(acc[mt][nt][2], acc[mt][nt][3]);
        }
    }
}

// ---------------- ex/ey: float4 smem (stride 36) ----------------
__global__ void __launch_bounds__(256) k_exy() {
    int b = blockIdx.x;
    int h = b % HS;
    int ng = b / HS;
    int g = ng % GG, n = ng / GG;
    __shared__ __align__(16) float qs[48][36];
    __shared__ __align__(16) float pxs[95][36];
    __shared__ __align__(16) float pys[48][36];
    __shared__ float exm[48][49];
    __shared__ float eym[48][49];
    __shared__ float rmx[48], rmy[48];
    int t = threadIdx.x;
    for (int i = t; i < 48 * 32; i += 256) {
        int d = i / 48, w_ = i % 48;
        qs[w_][d] = g_qkv[(size_t)(g * DD + d) * COLS + n * PP + h * HS + w_];
    }
    for (int i = t; i < 95 * 8; i += 256) {
        int dl = i / 8, d4 = i % 8;
        *(float4*)&pxs[dl][d4 * 4] = *(const float4*)&g_px[dl * CC + g * DD + d4 * 4];
    }
    for (int i = t; i < 48 * 8; i += 256) {
        int u = i / 8, d4 = i % 8;
        *(float4*)&pys[u][d4 * 4] = *(const float4*)&g_py[(h - u + 47) * CC + g * DD + d4 * 4];
    }
    __syncthreads();
    for (int i = t; i < PP; i += 256) {
        int w_ = i / 48, v = i % 48;
        float s = 0.f, s2 = 0.f;
#pragma unroll
        for (int d4 = 0; d4 < 8; d4++) {
            float4 q4 = *(const float4*)&qs[w_][d4 * 4];
            float4 px4 = *(const float4*)&pxs[w_ - v + 47][d4 * 4];
            float4 py4 = *(const float4*)&pys[v][d4 * 4];
            s += q4.x * px4.x + q4.y * px4.y + q4.z * px4.z + q4.w * px4.w;
            s2 += q4.x * py4.x + q4.y * py4.y + q4.z * py4.z + q4.w * py4.w;
        }
        exm[w_][v] = s;
        eym[w_][v] = s2;
    }
    __syncthreads();
    if (t < 48) {
        float m = -1e30f;
        for (int v = 0; v < 48; v++) m = fmaxf(m, exm[t][v]);
        rmx[t] = m;
    } else if (t < 96) {
        int w_ = t - 48;
        float m = -1e30f;
        for (int u = 0; u < 48; u++) m = fmaxf(m, eym[w_][u]);
        rmy[w_] = m;
    }
    __syncthreads();
    for (int i = t; i < PP; i += 256) {
        int w_ = i / 48, v = i % 48;
        g_ex[((size_t)ng * PP + h * HS + w_) * 48 + v] = expf(exm[w_][v] - rmx[w_]);
    }
    for (int i = t; i < PP; i += 256) {
        int u = i / 48, w_ = i % 48;
        g_eyT[((size_t)ng * 48 + u) * PP + h * HS + w_] = expf(eym[w_][u] - rmy[w_]);
    }
}

// ---------------- ek fused: dot + max + exp ----------------
__global__ void __launch_bounds__(256) k_ekf(const float* __restrict__ ab) {
    __shared__ float red[256];
    int ng = blockIdx.x;
    int g = ng % GG, n = ng / GG;
    int t = threadIdx.x;
    float ekv[9];
    float m = -1e30f;
#pragma unroll
    for (int j = 0; j < 9; j++) {
        int uv = j * 256 + t;
        float s = 0.f;
#pragma unroll
        for (int d = 0; d < 32; d++)
            s += ab[g * DD + d] * g_qkv[(size_t)(CC + g * DD + d) * COLS + n * PP + uv];
        ekv[j] = s;
        m = fmaxf(m, s);
    }
    red[t] = m;
    __syncthreads();
    for (int s = 128; s > 0; s >>= 1) {
        if (t < s) red[t] = fmaxf(red[t], red[t + s]);
        __syncthreads();
    }
    float mk = red[0];
#pragma unroll
    for (int j = 0; j < 9; j++) g_ek[(size_t)ng * PP + j * 256 + t] = expf(ekv[j] - mk);
}

// ---------------- Wt bf16 [ng][u][33][48], flat 8/thread ----------------
__global__ void k_wt8() {
    int i = (blockIdx.x * 256 + threadIdx.x) * 8;
    int v = i % 48;
    int d = (i / 48) % DPW;
    int u = (i / (48 * DPW)) % 48;
    int ng = i / (48 * DPW * 48);
    int g = ng % GG, n = ng / GG;
    size_t eko = (size_t)ng * PP + u * 48 + v;
    float4 e0 = *(const float4*)&g_ek[eko];
    float4 e1 = *(const float4*)&g_ek[eko + 4];
    unsigned r[4];
    if (d < 32) {
        size_t vo = (size_t)(2 * CC + g * DD + d) * COLS + n * PP + u * 48 + v;
        float4 v0 = *(const float4*)&g_qkv[vo];
        float4 v1 = *(const float4*)&g_qkv[vo + 4];
        r[0] = pack2(make_float2(e0.x * v0.x, e0.y * v0.y));
        r[1] = pack2(make_float2(e0.z * v0.z, e0.w * v0.w));
        r[2] = pack2(make_float2(e1.x * v1.x, e1.y * v1.y));
        r[3] = pack2(make_float2(e1.z * v1.z, e1.w * v1.w));
    } else {
        r[0] = pack2(make_float2(e0.x, e0.y));
        r[1] = pack2(make_float2(e0.z, e0.w));
        r[2] = pack2(make_float2(e1.x, e1.y));
        r[3] = pack2(make_float2(e1.z, e1.w));
    }
    *(uint4*)&g_wt[i] = *(uint4*)r;
}

// ---------------- attention + Z fused in MMA (256 thr, scalar LDS) ----------
#define WT_BUF (8 * 40 * 56)
#define ATT_SMEM (24576 + 2 * WT_BUF * 2)
__global__ void __launch_bounds__(256) k_attn_mma() {
    extern __shared__ __align__(16) char sm[];
    __nv_bfloat16* Eys = (__nv_bfloat16*)sm;
    __nv_bfloat16* Wth = (__nv_bfloat16*)(sm + 24576);
    int ng = blockIdx.y;
    int q0 = blockIdx.x * 256;
    int t = threadIdx.x, lane = t & 31, wid = t >> 5;
    int g = lane >> 2, tg = lane & 3;
    const __nv_bfloat16* wt_g = g_wt + (size_t)ng * 48 * DPW * 48;
    {
        unsigned* wz = (unsigned*)Wth;
        for (int j = t; j < 3136; j += 256) {
            int cc = j % 28;
            int row = j / 28;
            int uu = row % 8;
            int dd = 33 + (row / 8) % 7;
            int bb = row / 56;
            wz[bb * (WT_BUF / 2) + (uu * 40 + dd) * 28 + cc] = 0u;
        }
    }
    for (int j = t; j < 1584; j += 256) {
        int vq = j % 6, dd = (j / 6) % 33, uu = j / 198;
        cpa16(&Wth[(uu * 40 + dd) * 56 + vq * 8],
              wt_g + ((size_t)uu * DPW + dd) * 48 + vq * 8);
    }
    CPA_COMMIT;
    for (int i = t; i < 48 * 128; i += 256) {
        int u = i >> 7, qp = i & 127;
        float2 v2 = *(const float2*)&g_eyT[((size_t)ng * 48 + u) * PP + q0 + qp * 2];
        *(unsigned*)&Eys[u * 256 + qp * 2] = pack2(v2);
    }
    int qw = q0 + wid * 32;
    const float* exb = g_ex + (size_t)ng * PP * 48;
    unsigned exh[2][3][4];
#pragma unroll
    for (int mt = 0; mt < 2; mt++) {
        int qr0 = qw + mt * 16 + g, qr1 = qr0 + 8;
#pragma unroll
        for (int ks = 0; ks < 3; ks++) {
            int v0 = ks * 16 + tg * 2;
            exh[mt][ks][0] = pack2(*(const float2*)&exb[(size_t)qr0 * 48 + v0]);
            exh[mt][ks][1] = pack2(*(const float2*)&exb[(size_t)qr1 * 48 + v0]);
            exh[mt][ks][2] = pack2(*(const float2*)&exb[(size_t)qr0 * 48 + v0 + 8]);
            exh[mt][ks][3] = pack2(*(const float2*)&exb[(size_t)qr1 * 48 + v0 + 8]);
        }
    }
    float acc[2][5][4] = {};
    for (int it = 0; it < 6; it++) {
        int cur = it & 1, nxt = cur ^ 1;
        if (it < 5) {
            int uc = (it + 1) * 8;
            for (int j = t; j < 1584; j += 256) {
                int vq = j % 6, dd = (j / 6) % 33, uu = j / 198;
                cpa16(&Wth[nxt * WT_BUF + (uu * 40 + dd) * 56 + vq * 8],
                      wt_g + ((size_t)(uc + uu) * DPW + dd) * 48 + vq * 8);
            }
            CPA_COMMIT;
            CPA_WAIT1;
        } else {
            CPA_WAIT0;
        }
        __syncthreads();
#pragma unroll
        for (int uu = 0; uu < 8; uu++) {
            int u = it * 8 + uu;
            unsigned sa[2][3][4];
#pragma unroll
            for (int mt = 0; mt < 2; mt++) {
                __nv_bfloat162 e0 =
                    __bfloat162bfloat162(Eys[u * 256 + wid * 32 + mt * 16 + g]);
                __nv_bfloat162 e1 =
                    __bfloat162bfloat162(Eys[u * 256 + wid * 32 + mt * 16 + g + 8]);
#pragma unroll
                for (int ks = 0; ks < 3; ks++) {
                    sa[mt][ks][0] = hmul2u(exh[mt][ks][0], e0);
                    sa[mt][ks][1] = hmul2u(exh[mt][ks][1], e1);
                    sa[mt][ks][2] = hmul2u(exh[mt][ks][2], e0);
                    sa[mt][ks][3] = hmul2u(exh[mt][ks][3], e1);
                }
            }
            const unsigned* pbh = (const unsigned*)(Wth + cur * WT_BUF + uu * 40 * 56);
#pragma unroll
            for (int nt = 0; nt < 5; nt++) {
#pragma unroll
                for (int ks = 0; ks < 3; ks++) {
                    int widx = (nt * 8 + g) * 28 + ks * 8 + tg;
                    unsigned b0 = pbh[widx], b1 = pbh[widx + 4];
                    mma16816(acc[0][nt], sa[0][ks], b0, b1);
                    mma16816(acc[1][nt], sa[1][ks], b0, b1);
                }
            }
        }
        __syncthreads();
    }
    int n = ng >> 3, gh = ng & 7;
    int src = (lane >> 2) << 2;
#pragma unroll
    for (int mt = 0; mt < 2; mt++) {
        int qr0 = qw + mt * 16 + g, qr1 = qr0 + 8;
        float z0 = __shfl_sync(0xffffffffu, acc[mt][4][0], src);
        float z1 = __shfl_sync(0xffffffffu, acc[mt][4][2], src);
        float zi0 = 1.0f / z0, zi1 = 1.0f / z1;
        size_t col0 = (size_t)(n * PP + qr0) * CC;
        size_t col1 = (size_t)(n * PP + qr1) * CC;
#pragma unroll
        for (int nt = 0; nt < 4; nt++) {
            int c = gh * DD + nt * 8 + tg * 2;
            __nv_bfloat162 b0 = __float22bfloat162_rn(
                make_float2(acc[mt][nt][0] * zi0, acc[mt][nt][1] * zi0));
            __nv_bfloat162 b1 = __float22bfloat162_rn(
                make_float2(acc[mt][nt][2] * zi1, acc[mt][nt][3] * zi1));
            *(__nv_bfloat162*)&g_attT[col0 + c] = b0;
            *(__nv_bfloat162*)&g_attT[col1 + c] = b1;
        }
    }
}

// ---------------- bilinear upsample + bias + residual, 4-wide ----------------
__device__ __forceinline__ void taps48(int o, int& i0, int& i1, float& w0, float& w1) {
    int tt = o >> 1;
    if ((o & 1) == 0) {
        if (tt == 0) { i0 = 0; i1 = 0; w0 = 1.f; w1 = 0.f; }
        else { i0 = tt - 1; i1 = tt; w0 = 0.25f; w1 = 0.75f; }
    } else {
        if (tt == 47) { i0 = 47; i1 = 47; w0 = 1.f; w1 = 0.f; }
        else { i0 = tt; i1 = tt + 1; w0 = 0.75f; w1 = 0.25f; }
    }
}

__global__ void k_final4(const float* __restrict__ x, const float* __restrict__ bp,
                         const float* __restrict__ gamma, float* __restrict__ out) {
    int e = (blockIdx.x * 256 + threadIdx.x) * 4;
    int j0 = e % WW;
    int r = (e / WW) % HH;
    int c = (e / (HH * WW)) % CC;
    int n = e / (CC * HH * WW);
    int r0, r1;
    float rw0, rw1;
    taps48(r, r0, r1, rw0, rw1);
    const float* pr0 = g_proj + (size_t)c * COLS + n * PP + r0 * HS;
    const float* pr1 = g_proj + (size_t)c * COLS + n * PP + r1 * HS;
    float4 xr = *(const float4*)&x[e];
    float gmv = gamma[0];
    float bpv = bp[c];
    float res[4];
    float xv[4] = {xr.x, xr.y, xr.z, xr.w};
#pragma unroll
    for (int jj = 0; jj < 4; jj++) {
        int c0, c1;
        float cw0, cw1;
        taps48(j0 + jj, c0, c1, cw0, cw1);
        float v00 = pr0[c0], v01 = pr0[c1];
        float v10 = pr1[c0], v11 = pr1[c1];
        float bi = rw0 * (cw0 * v00 + cw1 * v01) + rw1 * (cw0 * v10 + cw1 * v11);
        res[jj] = gmv * (bi + bpv) + xv[jj];
    }
    *(float4*)&out[e] = make_float4(res[0], res[1], res[2], res[3]);
}

// ---------------- launch ----------------
extern "C" void kernel_launch(void* const* d_in, const int* in_sizes, int n_in,
                              void* d_out, int out_size) {
    (void)in_sizes; (void)n_in; (void)out_size;
    const float* x = (const float*)d_in[0];
    const float* Wq = (const float*)d_in[1];
    const float* Wk = (const float*)d_in[2];
    const float* Wv = (const float*)d_in[3];
    const float* Wx = (const float*)d_in[4];
    const float* Wy = (const float*)d_in[5];
    const float* ab = (const float*)d_in[6];
    const float* Wp = (const float*)d_in[7];
    const float* bp = (const float*)d_in[8];
    const float* gamma = (const float*)d_in[9];
    float* out = (float*)d_out;

    cudaFuncSetAttribute(k_attn_mma, cudaFuncAttributeMaxDynamicSharedMemorySize,
                         ATT_SMEM);
    cudaFuncSetAttribute(k_gemm_qkv, cudaFuncAttributeMaxDynamicSharedMemorySize,
                         QKV_SMEM);

    k_prep_w<<<384, 256>>>(Wq, Wk, Wv, Wp, Wx, Wy);
    k_subT<<<dim3(COLS / 32, CC / 32), 256>>>(x);
    k_pos2<<<dim3(95, 8), 256>>>();
    k_gemm_qkv<<<dim3(36, 3), 512, QKV_SMEM>>>();
    k_exy<<<16 * HS, 256>>>();
    k_ekf<<<16, 256>>>(ab);
    k_wt8<<<(16 * 48 * DPW * 48) / 2048, 256>>>();
    k_attn_mma<<<dim3(PP / 256, 16), 256, ATT_SMEM>>>();
    k_gemm_wp<<<dim3(36, 2), 256>>>();
    k_final4<<<(NN * CC * HH * WW) / 1024, 256>>>(x, bp, gamma, out);
}

// round 16
// speedup vs baseline: 1.6660x; 1.1285x over previous
#include <cuda_runtime.h>
#include <cuda_bf16.h>
#include <math.h>

#define NN 2
#define CC 256
#define HH 96
#define WW 96
#define HS 48
#define PP 2304
#define COLS 4608
#define GG 8
#define DD 32
#define DPW 33

// ---------------- scratch ----------------
__device__ __align__(16) __nv_bfloat16 g_wA[3 * CC * CC];
__device__ __align__(16) __nv_bfloat16 g_wp[CC * CC];
__device__ __align__(16) __nv_bfloat16 g_xsT[COLS * CC];
__device__ __align__(16) float g_qkv[3 * CC * COLS];
__device__ __align__(16) float g_px[95 * CC];
__device__ __align__(16) float g_py[95 * CC];
__device__ __align__(16) float g_wxt[128 * CC];
__device__ __align__(16) float g_wyt[128 * CC];
__device__ __align__(16) float g_ex[16 * PP * 48];
__device__ __align__(16) float g_eyT[16 * 48 * PP];
__device__ __align__(16) float g_ek[16 * PP];
__device__ __align__(16) __nv_bfloat16 g_wt[16 * 48 * DPW * 48];
__device__ __align__(16) __nv_bfloat16 g_attT[COLS * CC];
__device__ __align__(16) float g_proj[CC * COLS];

// ---------------- helpers ----------------
__device__ __forceinline__ unsigned pack2(float2 f) {
    __nv_bfloat162 h = __float22bfloat162_rn(f);
    return *reinterpret_cast<unsigned*>(&h);
}
__device__ __forceinline__ unsigned hmul2u(unsigned a, __nv_bfloat162 b) {
    __nv_bfloat162 av = *reinterpret_cast<__nv_bfloat162*>(&a);
    __nv_bfloat162 r = __hmul2(av, b);
    return *reinterpret_cast<unsigned*>(&r);
}
__device__ __forceinline__ void mma16816(float d[4], const unsigned a[4], unsigned b0,
                                         unsigned b1) {
    asm volatile(
        "mma.sync.aligned.m16n8k16.row.col.f32.bf16.bf16.f32 "
        "{%0,%1,%2,%3}, {%4,%5,%6,%7}, {%8,%9}, {%0,%1,%2,%3};\n"
        : "+f"(d[0]), "+f"(d[1]), "+f"(d[2]), "+f"(d[3])
        : "r"(a[0]), "r"(a[1]), "r"(a[2]), "r"(a[3]), "r"(b0), "r"(b1));
}
__device__ __forceinline__ void cpa16(void* smem, const void* gmem) {
    unsigned saddr = (unsigned)__cvta_generic_to_shared(smem);
    asm volatile("cp.async.ca.shared.global [%0], [%1], 16;\n" ::"r"(saddr), "l"(gmem));
}
#define CPA_COMMIT asm volatile("cp.async.commit_group;\n" ::)
#define CPA_WAIT1 asm volatile("cp.async.wait_group 1;\n" ::)
#define CPA_WAIT0 asm volatile("cp.async.wait_group 0;\n" ::)

// ---------------- fused prep: weight convert | subT | Wx/Wy transpose ----------
// blocks 0..255: weights; 256..1407: subsample+transpose x; 1408..1535: W transpose
__global__ void __launch_bounds__(256) k_prep(const float* __restrict__ Wq,
                                              const float* __restrict__ Wk,
                                              const float* __restrict__ Wv,
                                              const float* __restrict__ Wp,
                                              const float* __restrict__ Wx,
                                              const float* __restrict__ Wy,
                                              const float* __restrict__ x) {
    __shared__ float tile[32][33];
    int b = blockIdx.x, t = threadIdx.x;
    if (b < 256) {
        int i = b * 256 + t;
        g_wA[i] = __float2bfloat16(Wq[i]);
        g_wA[65536 + i] = __float2bfloat16(Wk[i]);
        g_wA[131072 + i] = __float2bfloat16(Wv[i]);
        g_wp[i] = __float2bfloat16(Wp[i]);
    } else if (b < 1408) {
        int bb = b - 256;
        int col0 = (bb % 144) * 32, c0 = (bb / 144) * 32;
        int tx = t % 32, ty = t / 32;
#pragma unroll
        for (int j = 0; j < 4; j++) {
            int c = c0 + ty + j * 8;
            int col = col0 + tx;
            int n = col / PP, p = col % PP;
            int ph = p / HS, pw = p % HS;
            tile[ty + j * 8][tx] = x[((n * CC + c) * HH + ph * 2) * WW + pw * 2];
        }
        __syncthreads();
#pragma unroll
        for (int j = 0; j < 4; j++) {
            int col = col0 + ty + j * 8;
            int c = c0 + tx;
            g_xsT[(size_t)col * CC + c] = __float2bfloat16(tile[tx][ty + j * 8]);
        }
    } else {
        int f = b - 1408;  // 0..127
        g_wxt[f * CC + t] = Wx[t * 128 + f];
        g_wyt[f * CC + t] = Wy[t * 128 + f];
    }
}

// ---------------- pos: grid (95, 8) ----------------
__global__ void __launch_bounds__(256) k_pos2() {
    __shared__ float bs[128];
    __shared__ float part[4][64];
    int dl = blockIdx.x;
    int y = blockIdx.y;
    int axis = y & 1;
    int quad = y >> 1;
    const float* w = axis ? g_wyt : g_wxt;
    float Dv = 2.0f * (float)(dl - 47);
    int t = threadIdx.x;
    if (t < 128) {
        int f = t & 63;
        float m = powf(1000.0f, (float)f * (1.0f / 64.0f));
        float a = Dv / m;
        bs[t] = (t < 64) ? sinf(a) : cosf(a);
    }
    __syncthreads();
    int chl = t & 63;
    int fg = t >> 6;
    int ch = quad * 64 + chl;
    float s = 0.f;
#pragma unroll
    for (int fo = 0; fo < 32; fo++) {
        int f = fg * 32 + fo;
        s += bs[f] * w[f * CC + ch];
    }
    part[fg][chl] = s;
    __syncthreads();
    if (t < 64) {
        float r = (part[0][t] + part[1][t]) + (part[2][t] + part[3][t]);
        float* dst = axis ? g_py : g_px;
        dst[dl * CC + quad * 64 + t] = r * 0.70710678118654752f;
    }
}

// ---------------- qkv GEMM: 256x128 tile, 512 thr ----------------
#define QKV_SMEM ((2 * 256 * 40 + 2 * 128 * 40) * 2)
__global__ void __launch_bounds__(512) k_gemm_qkv() {
    extern __shared__ __align__(16) __nv_bfloat16 qsm[];
    __nv_bfloat16* As = qsm;
    __nv_bfloat16* Bs = qsm + 2 * 256 * 40;
    int t = threadIdx.x, lane = t & 31, wid = t >> 5;
    int g = lane >> 2, tg = lane & 3;
    int wm = wid & 7, wn = wid >> 3;
    int m0 = blockIdx.y * 256, n0 = blockIdx.x * 128;
    float acc[2][8][4] = {};
#pragma unroll
    for (int jj = t; jj < 1536; jj += 512) {
        if (jj < 1024) {
            int row = jj >> 2, qv = jj & 3;
            cpa16(As + row * 40 + qv * 8, g_wA + (size_t)(m0 + row) * 256 + qv * 8);
        } else {
            int j2 = jj - 1024;
            int row = j2 >> 2, qv = j2 & 3;
            cpa16(Bs + row * 40 + qv * 8, g_xsT + (size_t)(n0 + row) * 256 + qv * 8);
        }
    }
    CPA_COMMIT;
    for (int it = 0; it < 8; it++) {
        int cur = it & 1, nxt = cur ^ 1;
        if (it < 7) {
            int kc = (it + 1) * 32;
#pragma unroll
            for (int jj = t; jj < 1536; jj += 512) {
                if (jj < 1024) {
                    int row = jj >> 2, qv = jj & 3;
                    cpa16(As + nxt * 10240 + row * 40 + qv * 8,
                          g_wA + (size_t)(m0 + row) * 256 + kc + qv * 8);
                } else {
                    int j2 = jj - 1024;
                    int row = j2 >> 2, qv = j2 & 3;
                    cpa16(Bs + nxt * 5120 + row * 40 + qv * 8,
                          g_xsT + (size_t)(n0 + row) * 256 + kc + qv * 8);
                }
            }
            CPA_COMMIT;
            CPA_WAIT1;
        } else {
            CPA_WAIT0;
        }
        __syncthreads();
#pragma unroll
        for (int k2 = 0; k2 < 2; k2++) {
            unsigned ah[2][4];
#pragma unroll
            for (int mt = 0; mt < 2; mt++) {
                int r = wm * 32 + mt * 16 + g;
                const unsigned* p0 = (const unsigned*)(As + cur * 10240 + r * 40);
                const unsigned* p1 = (const unsigned*)(As + cur * 10240 + (r + 8) * 40);
                ah[mt][0] = p0[k2 * 8 + tg];
                ah[mt][1] = p1[k2 * 8 + tg];
                ah[mt][2] = p0[k2 * 8 + 4 + tg];
                ah[mt][3] = p1[k2 * 8 + 4 + tg];
            }
#pragma unroll
            for (int nt = 0; nt < 8; nt++) {
                int nr = wn * 64 + nt * 8 + g;
                const unsigned* pbs = (const unsigned*)(Bs + cur * 5120 + nr * 40);
                unsigned b0 = pbs[k2 * 8 + tg], b1 = pbs[k2 * 8 + 4 + tg];
#pragma unroll
                for (int mt = 0; mt < 2; mt++) mma16816(acc[mt][nt], ah[mt], b0, b1);
            }
        }
        __syncthreads();
    }
#pragma unroll
    for (int mt = 0; mt < 2; mt++) {
        int r = m0 + wm * 32 + mt * 16 + g;
#pragma unroll
        for (int nt = 0; nt < 8; nt++) {
            int col = n0 + wn * 64 + nt * 8 + tg * 2;
            *(float2*)&g_qkv[(size_t)r * COLS + col] = make_float2(acc[mt][nt][0], acc[mt][nt][1]);
            *(float2*)&g_qkv[(size_t)(r + 8) * COLS + col] =
                make_float2(acc[mt][nt][2], acc[mt][nt][3]);
        }
    }
}

// ---------------- Wp GEMM: 128x128 tile, kc=32 ----------------
__global__ void __launch_bounds__(256) k_gemm_wp() {
    __shared__ __align__(16) __nv_bfloat16 As[2][128][40];
    __shared__ __align__(16) __nv_bfloat16 Bs[2][128][40];
    int t = threadIdx.x, lane = t & 31, wid = t >> 5;
    int g = lane >> 2, tg = lane & 3;
    int wm = wid & 3, wn = wid >> 2;
    int m0 = blockIdx.y * 128, n0 = blockIdx.x * 128;
    float acc[2][8][4] = {};
#pragma unroll
    for (int jj = t; jj < 512; jj += 256) {
        int row = jj >> 2, qv = jj & 3;
        cpa16(&As[0][row][qv * 8], g_wp + (size_t)(m0 + row) * 256 + qv * 8);
        cpa16(&Bs[0][row][qv * 8], g_attT + (size_t)(n0 + row) * 256 + qv * 8);
    }
    CPA_COMMIT;
    for (int it = 0; it < 8; it++) {
        int cur = it & 1, nxt = cur ^ 1;
        if (it < 7) {
            int kc = (it + 1) * 32;
#pragma unroll
            for (int jj = t; jj < 512; jj += 256) {
                int row = jj >> 2, qv = jj & 3;
                cpa16(&As[nxt][row][qv * 8], g_wp + (size_t)(m0 + row) * 256 + kc + qv * 8);
                cpa16(&Bs[nxt][row][qv * 8], g_attT + (size_t)(n0 + row) * 256 + kc + qv * 8);
            }
            CPA_COMMIT;
            CPA_WAIT1;
        } else {
            CPA_WAIT0;
        }
        __syncthreads();
#pragma unroll
        for (int k2 = 0; k2 < 2; k2++) {
            unsigned ah[2][4];
#pragma unroll
            for (int mt = 0; mt < 2; mt++) {
                int r = wm * 32 + mt * 16 + g;
                const unsigned* p0 = (const unsigned*)As[cur][r];
                const unsigned* p1 = (const unsigned*)As[cur][r + 8];
                ah[mt][0] = p0[k2 * 8 + tg];
                ah[mt][1] = p1[k2 * 8 + tg];
                ah[mt][2] = p0[k2 * 8 + 4 + tg];
                ah[mt][3] = p1[k2 * 8 + 4 + tg];
            }
#pragma unroll
            for (int nt = 0; nt < 8; nt++) {
                int nr = wn * 64 + nt * 8 + g;
                const unsigned* pbs = (const unsigned*)Bs[cur][nr];
                unsigned b0 = pbs[k2 * 8 + tg], b1 = pbs[k2 * 8 + 4 + tg];
#pragma unroll
                for (int mt = 0; mt < 2; mt++) mma16816(acc[mt][nt], ah[mt], b0, b1);
            }
        }
        __syncthreads();
    }
#pragma unroll
    for (int mt = 0; mt < 2; mt++) {
        int r = m0 + wm * 32 + mt * 16 + g;
#pragma unroll
        for (int nt = 0; nt < 8; nt++) {
            int col = n0 + wn * 64 + nt * 8 + tg * 2;
            *(float2*)&g_proj[(size_t)r * COLS + col] = make_float2(acc[mt][nt][0], acc[mt][nt][1]);
            *(float2*)&g_proj[(size_t)(r + 8) * COLS + col] =
                make_float2(acc[mt][nt][2], acc[mt][nt][3]);
        }
    }
}

// ---------------- fused ex/ey + ek: blocks 0..767 exy, 768..783 ek -------------
__global__ void __launch_bounds__(256) k_exy_ek(const float* __restrict__ ab) {
    __shared__ __align__(16) float qs[48][36];
    __shared__ __align__(16) float pxs[95][36];
    __shared__ __align__(16) float pys[48][36];
    __shared__ float exm[48][49];
    __shared__ float eym[48][49];
    __shared__ float rmx[48], rmy[48];
    int b = blockIdx.x;
    int t = threadIdx.x;
    if (b >= 16 * HS) {
        // ---- ek branch: dot + max + exp (red aliases qs) ----
        float* red = &qs[0][0];
        int ng = b - 16 * HS;
        int g = ng % GG, n = ng / GG;
        float ekv[9];
        float m = -1e30f;
#pragma unroll
        for (int j = 0; j < 9; j++) {
            int uv = j * 256 + t;
            float s = 0.f;
#pragma unroll
            for (int d = 0; d < 32; d++)
                s += ab[g * DD + d] * g_qkv[(size_t)(CC + g * DD + d) * COLS + n * PP + uv];
            ekv[j] = s;
            m = fmaxf(m, s);
        }
        red[t] = m;
        __syncthreads();
        for (int s = 128; s > 0; s >>= 1) {
            if (t < s) red[t] = fmaxf(red[t], red[t + s]);
            __syncthreads();
        }
        float mk = red[0];
#pragma unroll
        for (int j = 0; j < 9; j++) g_ek[(size_t)ng * PP + j * 256 + t] = expf(ekv[j] - mk);
        return;
    }
    int h = b % HS;
    int ng = b / HS;
    int g = ng % GG, n = ng / GG;
    for (int i = t; i < 48 * 32; i += 256) {
        int d = i / 48, w_ = i % 48;
        qs[w_][d] = g_qkv[(size_t)(g * DD + d) * COLS + n * PP + h * HS + w_];
    }
    for (int i = t; i < 95 * 8; i += 256) {
        int dl = i / 8, d4 = i % 8;
        *(float4*)&pxs[dl][d4 * 4] = *(const float4*)&g_px[dl * CC + g * DD + d4 * 4];
    }
    for (int i = t; i < 48 * 8; i += 256) {
        int u = i / 8, d4 = i % 8;
        *(float4*)&pys[u][d4 * 4] = *(const float4*)&g_py[(h - u + 47) * CC + g * DD + d4 * 4];
    }
    __syncthreads();
    for (int i = t; i < PP; i += 256) {
        int w_ = i / 48, v = i % 48;
        float s = 0.f, s2 = 0.f;
#pragma unroll
        for (int d4 = 0; d4 < 8; d4++) {
            float4 q4 = *(const float4*)&qs[w_][d4 * 4];
            float4 px4 = *(const float4*)&pxs[w_ - v + 47][d4 * 4];
            float4 py4 = *(const float4*)&pys[v][d4 * 4];
            s += q4.x * px4.x + q4.y * px4.y + q4.z * px4.z + q4.w * px4.w;
            s2 += q4.x * py4.x + q4.y * py4.y + q4.z * py4.z + q4.w * py4.w;
        }
        exm[w_][v] = s;
        eym[w_][v] = s2;
    }
    __syncthreads();
    if (t < 48) {
        float m = -1e30f;
        for (int v = 0; v < 48; v++) m = fmaxf(m, exm[t][v]);
        rmx[t] = m;
    } else if (t < 96) {
        int w_ = t - 48;
        float m = -1e30f;
        for (int u = 0; u < 48; u++) m = fmaxf(m, eym[w_][u]);
        rmy[w_] = m;
    }
    __syncthreads();
    for (int i = t; i < PP; i += 256) {
        int w_ = i / 48, v = i % 48;
        g_ex[((size_t)ng * PP + h * HS + w_) * 48 + v] = expf(exm[w_][v] - rmx[w_]);
    }
    for (int i = t; i < PP; i += 256) {
        int u = i / 48, w_ = i % 48;
        g_eyT[((size_t)ng * 48 + u) * PP + h * HS + w_] = expf(eym[w_][u] - rmy[w_]);
    }
}

// ---------------- Wt bf16 [ng][u][33][48], flat 8/thread ----------------
__global__ void k_wt8() {
    int i = (blockIdx.x * 256 + threadIdx.x) * 8;
    int v = i % 48;
    int d = (i / 48) % DPW;
    int u = (i / (48 * DPW)) % 48;
    int ng = i / (48 * DPW * 48);
    int g = ng % GG, n = ng / GG;
    size_t eko = (size_t)ng * PP + u * 48 + v;
    float4 e0 = *(const float4*)&g_ek[eko];
    float4 e1 = *(const float4*)&g_ek[eko + 4];
    unsigned r[4];
    if (d < 32) {
        size_t vo = (size_t)(2 * CC + g * DD + d) * COLS + n * PP + u * 48 + v;
        float4 v0 = *(const float4*)&g_qkv[vo];
        float4 v1 = *(const float4*)&g_qkv[vo + 4];
        r[0] = pack2(make_float2(e0.x * v0.x, e0.y * v0.y));
        r[1] = pack2(make_float2(e0.z * v0.z, e0.w * v0.w));
        r[2] = pack2(make_float2(e1.x * v1.x, e1.y * v1.y));
        r[3] = pack2(make_float2(e1.z * v1.z, e1.w * v1.w));
    } else {
        r[0] = pack2(make_float2(e0.x, e0.y));
        r[1] = pack2(make_float2(e0.z, e0.w));
        r[2] = pack2(make_float2(e1.x, e1.y));
        r[3] = pack2(make_float2(e1.z, e1.w));
    }
    *(uint4*)&g_wt[i] = *(uint4*)r;
}

// ---------------- attention + Z fused in MMA (256 thr, scalar LDS) ----------
#define WT_BUF (8 * 40 * 56)
#define ATT_SMEM (24576 + 2 * WT_BUF * 2)
__global__ void __launch_bounds__(256) k_attn_mma() {
    extern __shared__ __align__(16) char sm[];
    __nv_bfloat16* Eys = (__nv_bfloat16*)sm;
    __nv_bfloat16* Wth = (__nv_bfloat16*)(sm + 24576);
    int ng = blockIdx.y;
    int q0 = blockIdx.x * 256;
    int t = threadIdx.x, lane = t & 31, wid = t >> 5;
    int g = lane >> 2, tg = lane & 3;
    const __nv_bfloat16* wt_g = g_wt + (size_t)ng * 48 * DPW * 48;
    {
        unsigned* wz = (unsigned*)Wth;
        for (int j = t; j < 3136; j += 256) {
            int cc = j % 28;
            int row = j / 28;
            int uu = row % 8;
            int dd = 33 + (row / 8) % 7;
            int bb = row / 56;
            wz[bb * (WT_BUF / 2) + (uu * 40 + dd) * 28 + cc] = 0u;
        }
    }
    for (int j = t; j < 1584; j += 256) {
        int vq = j % 6, dd = (j / 6) % 33, uu = j / 198;
        cpa16(&Wth[(uu * 40 + dd) * 56 + vq * 8],
              wt_g + ((size_t)uu * DPW + dd) * 48 + vq * 8);
    }
    CPA_COMMIT;
    for (int i = t; i < 48 * 128; i += 256) {
        int u = i >> 7, qp = i & 127;
        float2 v2 = *(const float2*)&g_eyT[((size_t)ng * 48 + u) * PP + q0 + qp * 2];
        *(unsigned*)&Eys[u * 256 + qp * 2] = pack2(v2);
    }
    int qw = q0 + wid * 32;
    const float* exb = g_ex + (size_t)ng * PP * 48;
    unsigned exh[2][3][4];
#pragma unroll
    for (int mt = 0; mt < 2; mt++) {
        int qr0 = qw + mt * 16 + g, qr1 = qr0 + 8;
#pragma unroll
        for (int ks = 0; ks < 3; ks++) {
            int v0 = ks * 16 + tg * 2;
            exh[mt][ks][0] = pack2(*(const float2*)&exb[(size_t)qr0 * 48 + v0]);
            exh[mt][ks][1] = pack2(*(const float2*)&exb[(size_t)qr1 * 48 + v0]);
            exh[mt][ks][2] = pack2(*(const float2*)&exb[(size_t)qr0 * 48 + v0 + 8]);
            exh[mt][ks][3] = pack2(*(const float2*)&exb[(size_t)qr1 * 48 + v0 + 8]);
        }
    }
    float acc[2][5][4] = {};
    for (int it = 0; it < 6; it++) {
        int cur = it & 1, nxt = cur ^ 1;
        if (it < 5) {
            int uc = (it + 1) * 8;
            for (int j = t; j < 1584; j += 256) {
                int vq = j % 6, dd = (j / 6) % 33, uu = j / 198;
                cpa16(&Wth[nxt * WT_BUF + (uu * 40 + dd) * 56 + vq * 8],
                      wt_g + ((size_t)(uc + uu) * DPW + dd) * 48 + vq * 8);
            }
            CPA_COMMIT;
            CPA_WAIT1;
        } else {
            CPA_WAIT0;
        }
        __syncthreads();
#pragma unroll
        for (int uu = 0; uu < 8; uu++) {
            int u = it * 8 + uu;
            unsigned sa[2][3][4];
#pragma unroll
            for (int mt = 0; mt < 2; mt++) {
                __nv_bfloat162 e0 =
                    __bfloat162bfloat162(Eys[u * 256 + wid * 32 + mt * 16 + g]);
                __nv_bfloat162 e1 =
                    __bfloat162bfloat162(Eys[u * 256 + wid * 32 + mt * 16 + g + 8]);
#pragma unroll
                for (int ks = 0; ks < 3; ks++) {
                    sa[mt][ks][0] = hmul2u(exh[mt][ks][0], e0);
                    sa[mt][ks][1] = hmul2u(exh[mt][ks][1], e1);
                    sa[mt][ks][2] = hmul2u(exh[mt][ks][2], e0);
                    sa[mt][ks][3] = hmul2u(exh[mt][ks][3], e1);
                }
            }
            const unsigned* pbh = (const unsigned*)(Wth + cur * WT_BUF + uu * 40 * 56);
#pragma unroll
            for (int nt = 0; nt < 5; nt++) {
#pragma unroll
                for (int ks = 0; ks < 3; ks++) {
                    int widx = (nt * 8 + g) * 28 + ks * 8 + tg;
                    unsigned b0 = pbh[widx], b1 = pbh[widx + 4];
                    mma16816(acc[0][nt], sa[0][ks], b0, b1);
                    mma16816(acc[1][nt], sa[1][ks], b0, b1);
                }
            }
        }
        __syncthreads();
    }
    int n = ng >> 3, gh = ng & 7;
    int src = (lane >> 2) << 2;
#pragma unroll
    for (int mt = 0; mt < 2; mt++) {
        int qr0 = qw + mt * 16 + g, qr1 = qr0 + 8;
        float z0 = __shfl_sync(0xffffffffu, acc[mt][4][0], src);
        float z1 = __shfl_sync(0xffffffffu, acc[mt][4][2], src);
        float zi0 = 1.0f / z0, zi1 = 1.0f / z1;
        size_t col0 = (size_t)(n * PP + qr0) * CC;
        size_t col1 = (size_t)(n * PP + qr1) * CC;
#pragma unroll
        for (int nt = 0; nt < 4; nt++) {
            int c = gh * DD + nt * 8 + tg * 2;
            __nv_bfloat162 b0 = __float22bfloat162_rn(
                make_float2(acc[mt][nt][0] * zi0, acc[mt][nt][1] * zi0));
            __nv_bfloat162 b1 = __float22bfloat162_rn(
                make_float2(acc[mt][nt][2] * zi1, acc[mt][nt][3] * zi1));
            *(__nv_bfloat162*)&g_attT[col0 + c] = b0;
            *(__nv_bfloat162*)&g_attT[col1 + c] = b1;
        }
    }
}

// ---------------- bilinear upsample + bias + residual, 4-wide ----------------
__device__ __forceinline__ void taps48(int o, int& i0, int& i1, float& w0, float& w1) {
    int tt = o >> 1;
    if ((o & 1) == 0) {
        if (tt == 0) { i0 = 0; i1 = 0; w0 = 1.f; w1 = 0.f; }
        else { i0 = tt - 1; i1 = tt; w0 = 0.25f; w1 = 0.75f; }
    } else {
        if (tt == 47) { i0 = 47; i1 = 47; w0 = 1.f; w1 = 0.f; }
        else { i0 = tt; i1 = tt + 1; w0 = 0.75f; w1 = 0.25f; }
    }
}

__global__ void k_final4(const float* __restrict__ x, const float* __restrict__ bp,
                         const float* __restrict__ gamma, float* __restrict__ out) {
    int e = (blockIdx.x * 256 + threadIdx.x) * 4;
    int j0 = e % WW;
    int r = (e / WW) % HH;
    int c = (e / (HH * WW)) % CC;
    int n = e / (CC * HH * WW);
    int r0, r1;
    float rw0, rw1;
    taps48(r, r0, r1, rw0, rw1);
    const float* pr0 = g_proj + (size_t)c * COLS + n * PP + r0 * HS;
    const float* pr1 = g_proj + (size_t)c * COLS + n * PP + r1 * HS;
    float4 xr = *(const float4*)&x[e];
    float gmv = gamma[0];
    float bpv = bp[c];
    float res[4];
    float xv[4] = {xr.x, xr.y, xr.z, xr.w};
#pragma unroll
    for (int jj = 0; jj < 4; jj++) {
        int c0, c1;
        float cw0, cw1;
        taps48(j0 + jj, c0, c1, cw0, cw1);
        float v00 = pr0[c0], v01 = pr0[c1];
        float v10 = pr1[c0], v11 = pr1[c1];
        float bi = rw0 * (cw0 * v00 + cw1 * v01) + rw1 * (cw0 * v10 + cw1 * v11);
        res[jj] = gmv * (bi + bpv) + xv[jj];
    }
    *(float4*)&out[e] = make_float4(res[0], res[1], res[2], res[3]);
}

// ---------------- launch ----------------
extern "C" void kernel_launch(void* const* d_in, const int* in_sizes, int n_in,
                              void* d_out, int out_size) {
    (void)in_sizes; (void)n_in; (void)out_size;
    const float* x = (const float*)d_in[0];
    const float* Wq = (const float*)d_in[1];
    const float* Wk = (const float*)d_in[2];
    const float* Wv = (const float*)d_in[3];
    const float* Wx = (const float*)d_in[4];
    const float* Wy = (const float*)d_in[5];
    const float* ab = (const float*)d_in[6];
    const float* Wp = (const float*)d_in[7];
    const float* bp = (const float*)d_in[8];
    const float* gamma = (const float*)d_in[9];
    float* out = (float*)d_out;

    cudaFuncSetAttribute(k_attn_mma, cudaFuncAttributeMaxDynamicSharedMemorySize,
                         ATT_SMEM);
    cudaFuncSetAttribute(k_gemm_qkv, cudaFuncAttributeMaxDynamicSharedMemorySize,
                         QKV_SMEM);

    k_prep<<<1536, 256>>>(Wq, Wk, Wv, Wp, Wx, Wy, x);
    k_pos2<<<dim3(95, 8), 256>>>();
    k_gemm_qkv<<<dim3(36, 3), 512, QKV_SMEM>>>();
    k_exy_ek<<<16 * HS + 16, 256>>>(ab);
    k_wt8<<<(16 * 48 * DPW * 48) / 2048, 256>>>();
    k_attn_mma<<<dim3(PP / 256, 16), 256, ATT_SMEM>>>();
    k_gemm_wp<<<dim3(36, 2), 256>>>();
    k_final4<<<(NN * CC * HH * WW) / 1024, 256>>>(x, bp, gamma, out);
}

// round 17
// speedup vs baseline: 1.8221x; 1.0937x over previous
#include <cuda_runtime.h>
#include <cuda_bf16.h>
#include <math.h>

#define NN 2
#define CC 256
#define HH 96
#define WW 96
#define HS 48
#define PP 2304
#define COLS 4608
#define GG 8
#define DD 32
#define DPW 33

// ---------------- scratch ----------------
__device__ __align__(16) __nv_bfloat16 g_wA[3 * CC * CC];
__device__ __align__(16) __nv_bfloat16 g_wp[CC * CC];
__device__ __align__(16) __nv_bfloat16 g_xsT[COLS * CC];
__device__ __align__(16) float g_qkv[3 * CC * COLS];
__device__ __align__(16) float g_px[95 * CC];
__device__ __align__(16) float g_py[95 * CC];
__device__ __align__(16) float g_wxt[128 * CC];
__device__ __align__(16) float g_wyt[128 * CC];
__device__ __align__(16) float g_ex[16 * PP * 48];
__device__ __align__(16) float g_eyT[16 * 48 * PP];
__device__ __align__(16) float g_ek[16 * PP];
__device__ __align__(16) __nv_bfloat16 g_wt[16 * 48 * DPW * 48];
__device__ __align__(16) __nv_bfloat16 g_attT[COLS * CC];
__device__ __align__(16) float g_proj[CC * COLS];

// ---------------- helpers ----------------
__device__ __forceinline__ unsigned pack2(float2 f) {
    __nv_bfloat162 h = __float22bfloat162_rn(f);
    return *reinterpret_cast<unsigned*>(&h);
}
__device__ __forceinline__ unsigned hmul2u(unsigned a, __nv_bfloat162 b) {
    __nv_bfloat162 av = *reinterpret_cast<__nv_bfloat162*>(&a);
    __nv_bfloat162 r = __hmul2(av, b);
    return *reinterpret_cast<unsigned*>(&r);
}
__device__ __forceinline__ void mma16816(float d[4], const unsigned a[4], unsigned b0,
                                         unsigned b1) {
    asm volatile(
        "mma.sync.aligned.m16n8k16.row.col.f32.bf16.bf16.f32 "
        "{%0,%1,%2,%3}, {%4,%5,%6,%7}, {%8,%9}, {%0,%1,%2,%3};\n"
        : "+f"(d[0]), "+f"(d[1]), "+f"(d[2]), "+f"(d[3])
        : "r"(a[0]), "r"(a[1]), "r"(a[2]), "r"(a[3]), "r"(b0), "r"(b1));
}
__device__ __forceinline__ float dot4(float4 a, float4 b) {
    return a.x * b.x + a.y * b.y + a.z * b.z + a.w * b.w;
}
__device__ __forceinline__ void cpa16(void* smem, const void* gmem) {
    unsigned saddr = (unsigned)__cvta_generic_to_shared(smem);
    asm volatile("cp.async.ca.shared.global [%0], [%1], 16;\n" ::"r"(saddr), "l"(gmem));
}
#define CPA_COMMIT asm volatile("cp.async.commit_group;\n" ::)
#define CPA_WAIT1 asm volatile("cp.async.wait_group 1;\n" ::)
#define CPA_WAIT0 asm volatile("cp.async.wait_group 0;\n" ::)

// ---------------- fused prep ----------------
__global__ void __launch_bounds__(256) k_prep(const float* __restrict__ Wq,
                                              const float* __restrict__ Wk,
                                              const float* __restrict__ Wv,
                                              const float* __restrict__ Wp,
                                              const float* __restrict__ Wx,
                                              const float* __restrict__ Wy,
                                              const float* __restrict__ x) {
    __shared__ float tile[32][33];
    int b = blockIdx.x, t = threadIdx.x;
    if (b < 256) {
        int i = b * 256 + t;
        g_wA[i] = __float2bfloat16(Wq[i]);
        g_wA[65536 + i] = __float2bfloat16(Wk[i]);
        g_wA[131072 + i] = __float2bfloat16(Wv[i]);
        g_wp[i] = __float2bfloat16(Wp[i]);
    } else if (b < 1408) {
        int bb = b - 256;
        int col0 = (bb % 144) * 32, c0 = (bb / 144) * 32;
        int tx = t % 32, ty = t / 32;
#pragma unroll
        for (int j = 0; j < 4; j++) {
            int c = c0 + ty + j * 8;
            int col = col0 + tx;
            int n = col / PP, p = col % PP;
            int ph = p / HS, pw = p % HS;
            tile[ty + j * 8][tx] = x[((n * CC + c) * HH + ph * 2) * WW + pw * 2];
        }
        __syncthreads();
#pragma unroll
        for (int j = 0; j < 4; j++) {
            int col = col0 + ty + j * 8;
            int c = c0 + tx;
            g_xsT[(size_t)col * CC + c] = __float2bfloat16(tile[tx][ty + j * 8]);
        }
    } else {
        int f = b - 1408;
        g_wxt[f * CC + t] = Wx[t * 128 + f];
        g_wyt[f * CC + t] = Wy[t * 128 + f];
    }
}

// ---------------- pos: grid (95, 8) ----------------
__global__ void __launch_bounds__(256) k_pos2() {
    __shared__ float bs[128];
    __shared__ float part[4][64];
    int dl = blockIdx.x;
    int y = blockIdx.y;
    int axis = y & 1;
    int quad = y >> 1;
    const float* w = axis ? g_wyt : g_wxt;
    float Dv = 2.0f * (float)(dl - 47);
    int t = threadIdx.x;
    if (t < 128) {
        int f = t & 63;
        float m = powf(1000.0f, (float)f * (1.0f / 64.0f));
        float a = Dv / m;
        bs[t] = (t < 64) ? sinf(a) : cosf(a);
    }
    __syncthreads();
    int chl = t & 63;
    int fg = t >> 6;
    int ch = quad * 64 + chl;
    float s = 0.f;
#pragma unroll
    for (int fo = 0; fo < 32; fo++) {
        int f = fg * 32 + fo;
        s += bs[f] * w[f * CC + ch];
    }
    part[fg][chl] = s;
    __syncthreads();
    if (t < 64) {
        float r = (part[0][t] + part[1][t]) + (part[2][t] + part[3][t]);
        float* dst = axis ? g_py : g_px;
        dst[dl * CC + quad * 64 + t] = r * 0.70710678118654752f;
    }
}

// ---------------- qkv GEMM: 256x128 tile, 512 thr ----------------
#define QKV_SMEM ((2 * 256 * 40 + 2 * 128 * 40) * 2)
__global__ void __launch_bounds__(512) k_gemm_qkv() {
    extern __shared__ __align__(16) __nv_bfloat16 qsm[];
    __nv_bfloat16* As = qsm;
    __nv_bfloat16* Bs = qsm + 2 * 256 * 40;
    int t = threadIdx.x, lane = t & 31, wid = t >> 5;
    int g = lane >> 2, tg = lane & 3;
    int wm = wid & 7, wn = wid >> 3;
    int m0 = blockIdx.y * 256, n0 = blockIdx.x * 128;
    float acc[2][8][4] = {};
#pragma unroll
    for (int jj = t; jj < 1536; jj += 512) {
        if (jj < 1024) {
            int row = jj >> 2, qv = jj & 3;
            cpa16(As + row * 40 + qv * 8, g_wA + (size_t)(m0 + row) * 256 + qv * 8);
        } else {
            int j2 = jj - 1024;
            int row = j2 >> 2, qv = j2 & 3;
            cpa16(Bs + row * 40 + qv * 8, g_xsT + (size_t)(n0 + row) * 256 + qv * 8);
        }
    }
    CPA_COMMIT;
    for (int it = 0; it < 8; it++) {
        int cur = it & 1, nxt = cur ^ 1;
        if (it < 7) {
            int kc = (it + 1) * 32;
#pragma unroll
            for (int jj = t; jj < 1536; jj += 512) {
                if (jj < 1024) {
                    int row = jj >> 2, qv = jj & 3;
                    cpa16(As + nxt * 10240 + row * 40 + qv * 8,
                          g_wA + (size_t)(m0 + row) * 256 + kc + qv * 8);
                } else {
                    int j2 = jj - 1024;
                    int row = j2 >> 2, qv = j2 & 3;
                    cpa16(Bs + nxt * 5120 + row * 40 + qv * 8,
                          g_xsT + (size_t)(n0 + row) * 256 + kc + qv * 8);
                }
            }
            CPA_COMMIT;
            CPA_WAIT1;
        } else {
            CPA_WAIT0;
        }
        __syncthreads();
#pragma unroll
        for (int k2 = 0; k2 < 2; k2++) {
            unsigned ah[2][4];
#pragma unroll
            for (int mt = 0; mt < 2; mt++) {
                int r = wm * 32 + mt * 16 + g;
                const unsigned* p0 = (const unsigned*)(As + cur * 10240 + r * 40);
                const unsigned* p1 = (const unsigned*)(As + cur * 10240 + (r + 8) * 40);
                ah[mt][0] = p0[k2 * 8 + tg];
                ah[mt][1] = p1[k2 * 8 + tg];
                ah[mt][2] = p0[k2 * 8 + 4 + tg];
                ah[mt][3] = p1[k2 * 8 + 4 + tg];
            }
#pragma unroll
            for (int nt = 0; nt < 8; nt++) {
                int nr = wn * 64 + nt * 8 + g;
                const unsigned* pbs = (const unsigned*)(Bs + cur * 5120 + nr * 40);
                unsigned b0 = pbs[k2 * 8 + tg], b1 = pbs[k2 * 8 + 4 + tg];
#pragma unroll
                for (int mt = 0; mt < 2; mt++) mma16816(acc[mt][nt], ah[mt], b0, b1);
            }
        }
        __syncthreads();
    }
#pragma unroll
    for (int mt = 0; mt < 2; mt++) {
        int r = m0 + wm * 32 + mt * 16 + g;
#pragma unroll
        for (int nt = 0; nt < 8; nt++) {
            int col = n0 + wn * 64 + nt * 8 + tg * 2;
            *(float2*)&g_qkv[(size_t)r * COLS + col] = make_float2(acc[mt][nt][0], acc[mt][nt][1]);
            *(float2*)&g_qkv[(size_t)(r + 8) * COLS + col] =
                make_float2(acc[mt][nt][2], acc[mt][nt][3]);
        }
    }
}

// ---------------- Wp GEMM: 128x128 tile, kc=32 ----------------
__global__ void __launch_bounds__(256) k_gemm_wp() {
    __shared__ __align__(16) __nv_bfloat16 As[2][128][40];
    __shared__ __align__(16) __nv_bfloat16 Bs[2][128][40];
    int t = threadIdx.x, lane = t & 31, wid = t >> 5;
    int g = lane >> 2, tg = lane & 3;
    int wm = wid & 3, wn = wid >> 2;
    int m0 = blockIdx.y * 128, n0 = blockIdx.x * 128;
    float acc[2][8][4] = {};
#pragma unroll
    for (int jj = t; jj < 512; jj += 256) {
        int row = jj >> 2, qv = jj & 3;
        cpa16(&As[0][row][qv * 8], g_wp + (size_t)(m0 + row) * 256 + qv * 8);
        cpa16(&Bs[0][row][qv * 8], g_attT + (size_t)(n0 + row) * 256 + qv * 8);
    }
    CPA_COMMIT;
    for (int it = 0; it < 8; it++) {
        int cur = it & 1, nxt = cur ^ 1;
        if (it < 7) {
            int kc = (it + 1) * 32;
#pragma unroll
            for (int jj = t; jj < 512; jj += 256) {
                int row = jj >> 2, qv = jj & 3;
                cpa16(&As[nxt][row][qv * 8], g_wp + (size_t)(m0 + row) * 256 + kc + qv * 8);
                cpa16(&Bs[nxt][row][qv * 8], g_attT + (size_t)(n0 + row) * 256 + kc + qv * 8);
            }
            CPA_COMMIT;
            CPA_WAIT1;
        } else {
            CPA_WAIT0;
        }
        __syncthreads();
#pragma unroll
        for (int k2 = 0; k2 < 2; k2++) {
            unsigned ah[2][4];
#pragma unroll
            for (int mt = 0; mt < 2; mt++) {
                int r = wm * 32 + mt * 16 + g;
                const unsigned* p0 = (const unsigned*)As[cur][r];
                const unsigned* p1 = (const unsigned*)As[cur][r + 8];
                ah[mt][0] = p0[k2 * 8 + tg];
                ah[mt][1] = p1[k2 * 8 + tg];
                ah[mt][2] = p0[k2 * 8 + 4 + tg];
                ah[mt][3] = p1[k2 * 8 + 4 + tg];
            }
#pragma unroll
            for (int nt = 0; nt < 8; nt++) {
                int nr = wn * 64 + nt * 8 + g;
                const unsigned* pbs = (const unsigned*)Bs[cur][nr];
                unsigned b0 = pbs[k2 * 8 + tg], b1 = pbs[k2 * 8 + 4 + tg];
#pragma unroll
                for (int mt = 0; mt < 2; mt++) mma16816(acc[mt][nt], ah[mt], b0, b1);
            }
        }
        __syncthreads();
    }
#pragma unroll
    for (int mt = 0; mt < 2; mt++) {
        int r = m0 + wm * 32 + mt * 16 + g;
#pragma unroll
        for (int nt = 0; nt < 8; nt++) {
            int col = n0 + wn * 64 + nt * 8 + tg * 2;
            *(float2*)&g_proj[(size_t)r * COLS + col] = make_float2(acc[mt][nt][0], acc[mt][nt][1]);
            *(float2*)&g_proj[(size_t)(r + 8) * COLS + col] =
                make_float2(acc[mt][nt][2], acc[mt][nt][3]);
        }
    }
}

// ---------------- fused ex/ey (3x3 register tiles) + ek -------------------------
__global__ void __launch_bounds__(256) k_exy_ek(const float* __restrict__ ab) {
    __shared__ __align__(16) float qs[48][36];
    __shared__ __align__(16) float pxs[95][36];
    __shared__ __align__(16) float pys[48][36];
    __shared__ float exm[48][49];
    __shared__ float eym[48][49];
    __shared__ float rmx[48], rmy[48];
    int b = blockIdx.x;
    int t = threadIdx.x;
    if (b >= 16 * HS) {
        float* red = &qs[0][0];
        int ng = b - 16 * HS;
        int g = ng % GG, n = ng / GG;
        float ekv[9];
        float m = -1e30f;
#pragma unroll
        for (int j = 0; j < 9; j++) {
            int uv = j * 256 + t;
            float s = 0.f;
#pragma unroll
            for (int d = 0; d < 32; d++)
                s += ab[g * DD + d] * g_qkv[(size_t)(CC + g * DD + d) * COLS + n * PP + uv];
            ekv[j] = s;
            m = fmaxf(m, s);
        }
        red[t] = m;
        __syncthreads();
        for (int s = 128; s > 0; s >>= 1) {
            if (t < s) red[t] = fmaxf(red[t], red[t + s]);
            __syncthreads();
        }
        float mk = red[0];
#pragma unroll
        for (int j = 0; j < 9; j++) g_ek[(size_t)ng * PP + j * 256 + t] = expf(ekv[j] - mk);
        return;
    }
    int h = b % HS;
    int ng = b / HS;
    int g = ng % GG, n = ng / GG;
    for (int i = t; i < 48 * 32; i += 256) {
        int d = i / 48, w_ = i % 48;
        qs[w_][d] = g_qkv[(size_t)(g * DD + d) * COLS + n * PP + h * HS + w_];
    }
    for (int i = t; i < 95 * 8; i += 256) {
        int dl = i / 8, d4 = i % 8;
        *(float4*)&pxs[dl][d4 * 4] = *(const float4*)&g_px[dl * CC + g * DD + d4 * 4];
    }
    for (int i = t; i < 48 * 8; i += 256) {
        int u = i / 8, d4 = i % 8;
        *(float4*)&pys[u][d4 * 4] = *(const float4*)&g_py[(h - u + 47) * CC + g * DD + d4 * 4];
    }
    __syncthreads();
    // 3x3 register tile per thread: 256 threads = 16x16 tiles over 48x48
    {
        int tw = t >> 4, tv = t & 15;
        int w0 = tw * 3, v0 = tv * 3;
        int pb = w0 - v0 + 45;  // px row for (i - j + 2) offset
        float sx[3][3] = {}, sy[3][3] = {};
#pragma unroll
        for (int d4 = 0; d4 < 8; d4++) {
            float4 q4[3], px4[5], py4[3];
#pragma unroll
            for (int i = 0; i < 3; i++) q4[i] = *(const float4*)&qs[w0 + i][d4 * 4];
#pragma unroll
            for (int k = 0; k < 5; k++) px4[k] = *(const float4*)&pxs[pb + k][d4 * 4];
#pragma unroll
            for (int j = 0; j < 3; j++) py4[j] = *(const float4*)&pys[v0 + j][d4 * 4];
#pragma unroll
            for (int i = 0; i < 3; i++)
#pragma unroll
                for (int j = 0; j < 3; j++) {
                    sx[i][j] += dot4(q4[i], px4[i - j + 2]);
                    sy[i][j] += dot4(q4[i], py4[j]);
                }
        }
#pragma unroll
        for (int i = 0; i < 3; i++)
#pragma unroll
            for (int j = 0; j < 3; j++) {
                exm[w0 + i][v0 + j] = sx[i][j];
                eym[w0 + i][v0 + j] = sy[i][j];
            }
    }
    __syncthreads();
    if (t < 48) {
        float m = -1e30f;
        for (int v = 0; v < 48; v++) m = fmaxf(m, exm[t][v]);
        rmx[t] = m;
    } else if (t < 96) {
        int w_ = t - 48;
        float m = -1e30f;
        for (int u = 0; u < 48; u++) m = fmaxf(m, eym[w_][u]);
        rmy[w_] = m;
    }
    __syncthreads();
    for (int i = t; i < PP; i += 256) {
        int w_ = i / 48, v = i % 48;
        g_ex[((size_t)ng * PP + h * HS + w_) * 48 + v] = expf(exm[w_][v] - rmx[w_]);
    }
    for (int i = t; i < PP; i += 256) {
        int u = i / 48, w_ = i % 48;
        g_eyT[((size_t)ng * 48 + u) * PP + h * HS + w_] = expf(eym[w_][u] - rmy[w_]);
    }
}

// ---------------- Wt bf16 [ng][u][33][48], flat 8/thread ----------------
__global__ void k_wt8() {
    int i = (blockIdx.x * 256 + threadIdx.x) * 8;
    int v = i % 48;
    int d = (i / 48) % DPW;
    int u = (i / (48 * DPW)) % 48;
    int ng = i / (48 * DPW * 48);
    int g = ng % GG, n = ng / GG;
    size_t eko = (size_t)ng * PP + u * 48 + v;
    float4 e0 = *(const float4*)&g_ek[eko];
    float4 e1 = *(const float4*)&g_ek[eko + 4];
    unsigned r[4];
    if (d < 32) {
        size_t vo = (size_t)(2 * CC + g * DD + d) * COLS + n * PP + u * 48 + v;
        float4 v0 = *(const float4*)&g_qkv[vo];
        float4 v1 = *(const float4*)&g_qkv[vo + 4];
        r[0] = pack2(make_float2(e0.x * v0.x, e0.y * v0.y));
        r[1] = pack2(make_float2(e0.z * v0.z, e0.w * v0.w));
        r[2] = pack2(make_float2(e1.x * v1.x, e1.y * v1.y));
        r[3] = pack2(make_float2(e1.z * v1.z, e1.w * v1.w));
    } else {
        r[0] = pack2(make_float2(e0.x, e0.y));
        r[1] = pack2(make_float2(e0.z, e0.w));
        r[2] = pack2(make_float2(e1.x, e1.y));
        r[3] = pack2(make_float2(e1.z, e1.w));
    }
    *(uint4*)&g_wt[i] = *(uint4*)r;
}

// ---------------- attention + Z fused in MMA (256 thr, scalar LDS) ----------
#define WT_BUF (8 * 40 * 56)
#define ATT_SMEM (24576 + 2 * WT_BUF * 2)
__global__ void __launch_bounds__(256) k_attn_mma() {
    extern __shared__ __align__(16) char sm[];
    __nv_bfloat16* Eys = (__nv_bfloat16*)sm;
    __nv_bfloat16* Wth = (__nv_bfloat16*)(sm + 24576);
    int ng = blockIdx.y;
    int q0 = blockIdx.x * 256;
    int t = threadIdx.x, lane = t & 31, wid = t >> 5;
    int g = lane >> 2, tg = lane & 3;
    const __nv_bfloat16* wt_g = g_wt + (size_t)ng * 48 * DPW * 48;
    {
        unsigned* wz = (unsigned*)Wth;
        for (int j = t; j < 3136; j += 256) {
            int cc = j % 28;
            int row = j / 28;
            int uu = row % 8;
            int dd = 33 + (row / 8) % 7;
            int bb = row / 56;
            wz[bb * (WT_BUF / 2) + (uu * 40 + dd) * 28 + cc] = 0u;
        }
    }
    for (int j = t; j < 1584; j += 256) {
        int vq = j % 6, dd = (j / 6) % 33, uu = j / 198;
        cpa16(&Wth[(uu * 40 + dd) * 56 + vq * 8],
              wt_g + ((size_t)uu * DPW + dd) * 48 + vq * 8);
    }
    CPA_COMMIT;
    for (int i = t; i < 48 * 128; i += 256) {
        int u = i >> 7, qp = i & 127;
        float2 v2 = *(const float2*)&g_eyT[((size_t)ng * 48 + u) * PP + q0 + qp * 2];
        *(unsigned*)&Eys[u * 256 + qp * 2] = pack2(v2);
    }
    int qw = q0 + wid * 32;
    const float* exb = g_ex + (size_t)ng * PP * 48;
    unsigned exh[2][3][4];
#pragma unroll
    for (int mt = 0; mt < 2; mt++) {
        int qr0 = qw + mt * 16 + g, qr1 = qr0 + 8;
#pragma unroll
        for (int ks = 0; ks < 3; ks++) {
            int v0 = ks * 16 + tg * 2;
            exh[mt][ks][0] = pack2(*(const float2*)&exb[(size_t)qr0 * 48 + v0]);
            exh[mt][ks][1] = pack2(*(const float2*)&exb[(size_t)qr1 * 48 + v0]);
            exh[mt][ks][2] = pack2(*(const float2*)&exb[(size_t)qr0 * 48 + v0 + 8]);
            exh[mt][ks][3] = pack2(*(const float2*)&exb[(size_t)qr1 * 48 + v0 + 8]);
        }
    }
    float acc[2][5][4] = {};
    for (int it = 0; it < 6; it++) {
        int cur = it & 1, nxt = cur ^ 1;
        if (it < 5) {
            int uc = (it + 1) * 8;
            for (int j = t; j < 1584; j += 256) {
                int vq = j % 6, dd = (j / 6) % 33, uu = j / 198;
                cpa16(&Wth[nxt * WT_BUF + (uu * 40 + dd) * 56 + vq * 8],
                      wt_g + ((size_t)(uc + uu) * DPW + dd) * 48 + vq * 8);
            }
            CPA_COMMIT;
            CPA_WAIT1;
        } else {
            CPA_WAIT0;
        }
        __syncthreads();
#pragma unroll
        for (int uu = 0; uu < 8; uu++) {
            int u = it * 8 + uu;
            unsigned sa[2][3][4];
#pragma unroll
            for (int mt = 0; mt < 2; mt++) {
                __nv_bfloat162 e0 =
                    __bfloat162bfloat162(Eys[u * 256 + wid * 32 + mt * 16 + g]);
                __nv_bfloat162 e1 =
                    __bfloat162bfloat162(Eys[u * 256 + wid * 32 + mt * 16 + g + 8]);
#pragma unroll
                for (int ks = 0; ks < 3; ks++) {
                    sa[mt][ks][0] = hmul2u(exh[mt][ks][0], e0);
                    sa[mt][ks][1] = hmul2u(exh[mt][ks][1], e1);
                    sa[mt][ks][2] = hmul2u(exh[mt][ks][2], e0);
                    sa[mt][ks][3] = hmul2u(exh[mt][ks][3], e1);
                }
            }
            const unsigned* pbh = (const unsigned*)(Wth + cur * WT_BUF + uu * 40 * 56);
#pragma unroll
            for (int nt = 0; nt < 5; nt++) {
#pragma unroll
                for (int ks = 0; ks < 3; ks++) {
                    int widx = (nt * 8 + g) * 28 + ks * 8 + tg;
                    unsigned b0 = pbh[widx], b1 = pbh[widx + 4];
                    mma16816(acc[0][nt], sa[0][ks], b0, b1);
                    mma16816(acc[1][nt], sa[1][ks], b0, b1);
                }
            }
        }
        __syncthreads();
    }
    int n = ng >> 3, gh = ng & 7;
    int src = (lane >> 2) << 2;
#pragma unroll
    for (int mt = 0; mt < 2; mt++) {
        int qr0 = qw + mt * 16 + g, qr1 = qr0 + 8;
        float z0 = __shfl_sync(0xffffffffu, acc[mt][4][0], src);
        float z1 = __shfl_sync(0xffffffffu, acc[mt][4][2], src);
        float zi0 = 1.0f / z0, zi1 = 1.0f / z1;
        size_t col0 = (size_t)(n * PP + qr0) * CC;
        size_t col1 = (size_t)(n * PP + qr1) * CC;
#pragma unroll
        for (int nt = 0; nt < 4; nt++) {
            int c = gh * DD + nt * 8 + tg * 2;
            __nv_bfloat162 b0 = __float22bfloat162_rn(
                make_float2(acc[mt][nt][0] * zi0, acc[mt][nt][1] * zi0));
            __nv_bfloat162 b1 = __float22bfloat162_rn(
                make_float2(acc[mt][nt][2] * zi1, acc[mt][nt][3] * zi1));
            *(__nv_bfloat162*)&g_attT[col0 + c] = b0;
            *(__nv_bfloat162*)&g_attT[col1 + c] = b1;
        }
    }
}

// ---------------- bilinear upsample + bias + residual, 4-wide ----------------
__device__ __forceinline__ void taps48(int o, int& i0, int& i1, float& w0, float& w1) {
    int tt = o >> 1;
    if ((o & 1) == 0) {
        if (tt == 0) { i0 = 0; i1 = 0; w0 = 1.f; w1 = 0.f; }
        else { i0 = tt - 1; i1 = tt; w0 = 0.25f; w1 = 0.75f; }
    } else {
        if (tt == 47) { i0 = 47; i1 = 47; w0 = 1.f; w1 = 0.f; }
        else { i0 = tt; i1 = tt + 1; w0 = 0.75f; w1 = 0.25f; }
    }
}

__global__ void k_final4(const float* __restrict__ x, const float* __restrict__ bp,
                         const float* __restrict__ gamma, float* __restrict__ out) {
    int e = (blockIdx.x * 256 + threadIdx.x) * 4;
    int j0 = e % WW;
    int r = (e / WW) % HH;
    int c = (e / (HH * WW)) % CC;
    int n = e / (CC * HH * WW);
    int r0, r1;
    float rw0, rw1;
    taps48(r, r0, r1, rw0, rw1);
    const float* pr0 = g_proj + (size_t)c * COLS + n * PP + r0 * HS;
    const float* pr1 = g_proj + (size_t)c * COLS + n * PP + r1 * HS;
    float4 xr = *(const float4*)&x[e];
    float gmv = gamma[0];
    float bpv = bp[c];
    float res[4];
    float xv[4] = {xr.x, xr.y, xr.z, xr.w};
#pragma unroll
    for (int jj = 0; jj < 4; jj++) {
        int c0, c1;
        float cw0, cw1;
        taps48(j0 + jj, c0, c1, cw0, cw1);
        float v00 = pr0[c0], v01 = pr0[c1];
        float v10 = pr1[c0], v11 = pr1[c1];
        float bi = rw0 * (cw0 * v00 + cw1 * v01) + rw1 * (cw0 * v10 + cw1 * v11);
        res[jj] = gmv * (bi + bpv) + xv[jj];
    }
    *(float4*)&out[e] = make_float4(res[0], res[1], res[2], res[3]);
}

// ---------------- launch ----------------
extern "C" void kernel_launch(void* const* d_in, const int* in_sizes, int n_in,
                              void* d_out, int out_size) {
    (void)in_sizes; (void)n_in; (void)out_size;
    const float* x = (const float*)d_in[0];
    const float* Wq = (const float*)d_in[1];
    const float* Wk = (const float*)d_in[2];
    const float* Wv = (const float*)d_in[3];
    const float* Wx = (const float*)d_in[4];
    const float* Wy = (const float*)d_in[5];
    const float* ab = (const float*)d_in[6];
    const float* Wp = (const float*)d_in[7];
    const float* bp = (const float*)d_in[8];
    const float* gamma = (const float*)d_in[9];
    float* out = (float*)d_out;

    cudaFuncSetAttribute(k_attn_mma, cudaFuncAttributeMaxDynamicSharedMemorySize,
                         ATT_SMEM);
    cudaFuncSetAttribute(k_gemm_qkv, cudaFuncAttributeMaxDynamicSharedMemorySize,
                         QKV_SMEM);

    k_prep<<<1536, 256>>>(Wq, Wk, Wv, Wp, Wx, Wy, x);
    k_pos2<<<dim3(95, 8), 256>>>();
    k_gemm_qkv<<<dim3(36, 3), 512, QKV_SMEM>>>();
    k_exy_ek<<<16 * HS + 16, 256>>>(ab);
    k_wt8<<<(16 * 48 * DPW * 48) / 2048, 256>>>();
    k_attn_mma<<<dim3(PP / 256, 16), 256, ATT_SMEM>>>();
    k_gemm_wp<<<dim3(36, 2), 256>>>();
    k_final4<<<(NN * CC * HH * WW) / 1024, 256>>>(x, bp, gamma, out);
}